// round 1
// baseline (speedup 1.0000x reference)
#include <cuda_runtime.h>
#include <math.h>

#define BB 4
#define NN 1024
#define DD 1024
#define HH 16
#define HD 64
#define BH (BB*HH)

// Scratch (device globals — allocation-free per harness rules)
__device__ float g_q[BH*NN*HD];   // [B,H,N,hd]
__device__ float g_k[BH*NN*HD];
__device__ float g_v[BH*NN*HD];
__device__ float g_o[BB*NN*DD];   // [B,N,H*hd] (pre output-projection)

// out = X[M,K] @ W[Ncols,K]^T   (both K-major). M=4096, K=1024, Ncols=1024.
// MODE 0: out[m*1024 + c]   (plain row-major)
// MODE 1: out[((b*H+h)*N + n)*64 + t]  head-scatter (b=m>>10,n=m&1023,h=c>>6,t=c&63)
template<int MODE>
__global__ __launch_bounds__(256) void gemm_xt(
    const float* __restrict__ X, const float* __restrict__ W, float* __restrict__ out)
{
    __shared__ float As[16][68];
    __shared__ float Bs[16][68];
    const int tid = threadIdx.x;
    const int tx = tid & 15, ty = tid >> 4;
    const int m0 = blockIdx.y * 64, n0 = blockIdx.x * 64;
    const int lrow = tid >> 2, lq = tid & 3;
    const float* xp = X + (size_t)(m0 + lrow) * DD + lq * 4;
    const float* wp = W + (size_t)(n0 + lrow) * DD + lq * 4;
    float acc[4][4] = {};

    for (int k0 = 0; k0 < DD; k0 += 16) {
        float4 av = *(const float4*)(xp + k0);
        float4 bv = *(const float4*)(wp + k0);
        As[lq*4+0][lrow] = av.x; As[lq*4+1][lrow] = av.y;
        As[lq*4+2][lrow] = av.z; As[lq*4+3][lrow] = av.w;
        Bs[lq*4+0][lrow] = bv.x; Bs[lq*4+1][lrow] = bv.y;
        Bs[lq*4+2][lrow] = bv.z; Bs[lq*4+3][lrow] = bv.w;
        __syncthreads();
#pragma unroll
        for (int k = 0; k < 16; k++) {
            float4 a = *(const float4*)&As[k][ty*4];
            float4 b = *(const float4*)&Bs[k][tx*4];
            float ar[4] = {a.x, a.y, a.z, a.w};
            float br[4] = {b.x, b.y, b.z, b.w};
#pragma unroll
            for (int i = 0; i < 4; i++)
#pragma unroll
                for (int j = 0; j < 4; j++)
                    acc[i][j] += ar[i] * br[j];
        }
        __syncthreads();
    }

#pragma unroll
    for (int i = 0; i < 4; i++) {
        int m = m0 + ty*4 + i;
#pragma unroll
        for (int j = 0; j < 4; j++) {
            int c = n0 + tx*4 + j;
            if (MODE == 0) {
                out[(size_t)m * DD + c] = acc[i][j];
            } else {
                int b = m >> 10, n = m & 1023;
                int h = c >> 6,  t = c & 63;
                out[(size_t)((b*HH + h)*NN + n) * HD + t] = acc[i][j];
            }
        }
    }
}

// One block = one (b,h) x 32 query rows. Full 32x1024 score tile in smem.
__global__ __launch_bounds__(256) void attn_kernel(const float* __restrict__ bias,
                                                   float* __restrict__ out)
{
    extern __shared__ float sm[];
    float* ps  = sm;                 // [32][1024] scores / probs
    float* sQ  = sm + 32*1024;       // [32][65]
    float* sKV = sQ + 32*65;         // [64][68]  K^T chunk, then V chunk

    const int bh   = blockIdx.x;       // 0..63
    const int row0 = blockIdx.y * 32;  // query tile start
    const int tid  = threadIdx.x;
    const int tx = tid & 15, ty = tid >> 4;
    const int r0 = ty*2, r1 = ty*2 + 1;

    const float* q    = g_q + (size_t)bh*NN*HD + (size_t)row0*HD;
    const float* kptr = g_k + (size_t)bh*NN*HD;
    const float* vptr = g_v + (size_t)bh*NN*HD;
    const float* brow = bias + (size_t)bh*NN*NN + (size_t)row0*NN;

    // Load Q tile [32][64]
    for (int idx = tid; idx < 32*64; idx += 256)
        sQ[(idx >> 6)*65 + (idx & 63)] = q[idx];

    const float scale = 0.125f;  // hd^-0.5

    // ---- Phase 1: scores = Q K^T * scale + bias ----
    for (int kc = 0; kc < 16; kc++) {
        __syncthreads();  // sKV free to overwrite (also makes sQ visible at kc=0)
        // K chunk transposed: sKV[d][kl]
        for (int idx = tid; idx < 64*64; idx += 256) {
            int kl = idx >> 6, d = idx & 63;
            sKV[d*68 + kl] = kptr[(size_t)kc*4096 + idx];
        }
        __syncthreads();
        float c0[4] = {}, c1[4] = {};
#pragma unroll 16
        for (int d = 0; d < 64; d++) {
            float a0 = sQ[r0*65 + d];
            float a1 = sQ[r1*65 + d];
            float4 b = *(const float4*)&sKV[d*68 + tx*4];
            c0[0] += a0*b.x; c0[1] += a0*b.y; c0[2] += a0*b.z; c0[3] += a0*b.w;
            c1[0] += a1*b.x; c1[1] += a1*b.y; c1[2] += a1*b.z; c1[3] += a1*b.w;
        }
        int key = kc*64 + tx*4;
        float4 bi0 = *(const float4*)&brow[(size_t)r0*NN + key];
        float4 bi1 = *(const float4*)&brow[(size_t)r1*NN + key];
        float4 s0 = make_float4(fmaf(c0[0], scale, bi0.x), fmaf(c0[1], scale, bi0.y),
                                fmaf(c0[2], scale, bi0.z), fmaf(c0[3], scale, bi0.w));
        float4 s1 = make_float4(fmaf(c1[0], scale, bi1.x), fmaf(c1[1], scale, bi1.y),
                                fmaf(c1[2], scale, bi1.z), fmaf(c1[3], scale, bi1.w));
        *(float4*)&ps[r0*1024 + key] = s0;
        *(float4*)&ps[r1*1024 + key] = s1;
    }
    __syncthreads();

    // ---- Phase 2: row softmax (warp per row, 4 rows/warp) ----
    const int warp = tid >> 5, lane = tid & 31;
    for (int r = warp; r < 32; r += 8) {
        float* prow = ps + r*1024;
        float mx = -INFINITY;
        for (int i = lane; i < 1024; i += 32) mx = fmaxf(mx, prow[i]);
#pragma unroll
        for (int o = 16; o > 0; o >>= 1) mx = fmaxf(mx, __shfl_xor_sync(0xffffffffu, mx, o));
        float s = 0.f;
        for (int i = lane; i < 1024; i += 32) {
            float e = __expf(prow[i] - mx);
            prow[i] = e;
            s += e;
        }
#pragma unroll
        for (int o = 16; o > 0; o >>= 1) s += __shfl_xor_sync(0xffffffffu, s, o);
        float inv = 1.0f / s;
        for (int i = lane; i < 1024; i += 32) prow[i] *= inv;
    }

    // ---- Phase 3: O = P @ V ----
    float o0[4] = {}, o1[4] = {};
    for (int kc = 0; kc < 16; kc++) {
        __syncthreads();  // sKV free (first iter: also fences softmax writes)
        for (int idx = tid; idx < 64*64; idx += 256) {
            int kl = idx >> 6, t = idx & 63;
            sKV[kl*68 + t] = vptr[(size_t)kc*4096 + idx];
        }
        __syncthreads();
#pragma unroll 16
        for (int kk = 0; kk < 64; kk++) {
            float p0 = ps[r0*1024 + kc*64 + kk];
            float p1 = ps[r1*1024 + kc*64 + kk];
            float4 b = *(const float4*)&sKV[kk*68 + tx*4];
            o0[0] += p0*b.x; o0[1] += p0*b.y; o0[2] += p0*b.z; o0[3] += p0*b.w;
            o1[0] += p1*b.x; o1[1] += p1*b.y; o1[2] += p1*b.z; o1[3] += p1*b.w;
        }
    }

    // Write O in [B, N, H*hd] layout (ready for output projection)
    int b = bh >> 4, h = bh & 15;
    float* op = out + (size_t)(b*NN + row0)*DD + h*HD + tx*4;
    *(float4*)&op[(size_t)r0*DD] = make_float4(o0[0], o0[1], o0[2], o0[3]);
    *(float4*)&op[(size_t)r1*DD] = make_float4(o1[0], o1[1], o1[2], o1[3]);
}

extern "C" void kernel_launch(void* const* d_in, const int* in_sizes, int n_in,
                              void* d_out, int out_size)
{
    const float* x    = (const float*)d_in[0];
    const float* bias = (const float*)d_in[1];
    const float* Wq   = (const float*)d_in[2];
    const float* Wk   = (const float*)d_in[3];
    const float* Wv   = (const float*)d_in[4];
    const float* Wo   = (const float*)d_in[5];
    float* out = (float*)d_out;

    float *qb, *kb, *vb, *ob;
    cudaGetSymbolAddress((void**)&qb, g_q);
    cudaGetSymbolAddress((void**)&kb, g_k);
    cudaGetSymbolAddress((void**)&vb, g_v);
    cudaGetSymbolAddress((void**)&ob, g_o);

    const int SMEM_BYTES = (32*1024 + 32*65 + 64*68) * 4;  // 156800 B
    cudaFuncSetAttribute(attn_kernel, cudaFuncAttributeMaxDynamicSharedMemorySize, SMEM_BYTES);

    dim3 gg(DD/64, (BB*NN)/64);  // (16, 64)

    gemm_xt<1><<<gg, 256>>>(x, Wq, qb);
    gemm_xt<1><<<gg, 256>>>(x, Wk, kb);
    gemm_xt<1><<<gg, 256>>>(x, Wv, vb);

    attn_kernel<<<dim3(BH, NN/32), 256, SMEM_BYTES>>>(bias, ob);

    gemm_xt<0><<<gg, 256>>>(ob, Wo, out);
}

// round 7
// speedup vs baseline: 1.3484x; 1.3484x over previous
#include <cuda_runtime.h>
#include <cuda_bf16.h>
#include <math.h>
#include <stdint.h>

#define BB 4
#define NN 1024
#define DD 1024
#define HH 16
#define HD 64
#define BH (BB*HH)

// ---------------- scratch (device globals; allocation-free) ----------------
__device__ float g_q[BH*NN*HD];
__device__ float g_k[BH*NN*HD];
__device__ float g_v[BH*NN*HD];
__device__ float g_o[BB*NN*DD];

__device__ __nv_bfloat16 g_xh[BB*NN*DD];
__device__ __nv_bfloat16 g_xl[BB*NN*DD];
__device__ __nv_bfloat16 g_oh[BB*NN*DD];
__device__ __nv_bfloat16 g_ol[BB*NN*DD];
__device__ __nv_bfloat16 g_wh[4][DD*DD];
__device__ __nv_bfloat16 g_wl[4][DD*DD];

// ---------------- helpers ----------------
__device__ __forceinline__ uint32_t smem_u32(const void* p) {
    uint32_t a;
    asm("{ .reg .u64 t; cvta.to.shared.u64 t, %1; cvt.u32.u64 %0, t; }" : "=r"(a) : "l"(p));
    return a;
}
__device__ __forceinline__ void mma16816(float* d, const uint32_t* a, const uint32_t* b) {
    asm volatile(
        "mma.sync.aligned.m16n8k16.row.col.f32.bf16.bf16.f32 "
        "{%0,%1,%2,%3}, {%4,%5,%6,%7}, {%8,%9}, {%0,%1,%2,%3};"
        : "+f"(d[0]), "+f"(d[1]), "+f"(d[2]), "+f"(d[3])
        : "r"(a[0]), "r"(a[1]), "r"(a[2]), "r"(a[3]), "r"(b[0]), "r"(b[1]));
}
#define CP_ASYNC16(sdst, gsrc) \
    asm volatile("cp.async.cg.shared.global [%0], [%1], 16;" :: "r"(sdst), "l"(gsrc))
#define CP_COMMIT() asm volatile("cp.async.commit_group;" ::: "memory")
#define CP_WAIT0()  asm volatile("cp.async.wait_group 0;" ::: "memory")

// ---------------- fp32 -> bf16 hi/lo split ----------------
__global__ __launch_bounds__(256) void split_kernel(const float* __restrict__ s,
                                                    __nv_bfloat16* __restrict__ h,
                                                    __nv_bfloat16* __restrict__ l, int n)
{
    int i = blockIdx.x * 256 + threadIdx.x;
    if (i < n) {
        float v = s[i];
        __nv_bfloat16 hh = __float2bfloat16(v);
        h[i] = hh;
        l[i] = __float2bfloat16(v - __bfloat162float(hh));
    }
}

// ---------------- split-bf16 GEMM on mma.sync (HMMA) ----------------
// C[M,N] = A[M,K] @ B[N,K]^T,  A=Ah+Al, B=Bh+Bl (3-term).
// CTA tile 128x128, 8 warps of 64x32, K-stage 32, cp.async double buffer.
// MODE0: out[m*1024+n]   MODE1: out[((b*16+h)*1024+n)*64+t]
#define KS 32
#define SS 40                          // smem row stride in bf16 (80B, 16B-aligned)
#define TILE_BYTES (128*SS*2)          // 10240
#define STAGE_BYTES (4*TILE_BYTES)     // 40960: Ah, Al, Bh, Bl
#define GSMEM_BYTES (2*STAGE_BYTES)    // 81920

template<int MODE>
__global__ __launch_bounds__(256) void gemm_mma(
    const __nv_bfloat16* __restrict__ Ah, const __nv_bfloat16* __restrict__ Al,
    const __nv_bfloat16* __restrict__ Bh, const __nv_bfloat16* __restrict__ Bl,
    float* __restrict__ out)
{
    extern __shared__ __align__(16) char smem[];
    const int tid = threadIdx.x;
    const int wid = tid >> 5, lane = tid & 31;
    const int g = lane >> 2, tg = lane & 3;
    const int m0 = blockIdx.y * 128, n0 = blockIdx.x * 128;
    const int wm = (wid & 1) * 64, wn = (wid >> 1) * 32;

    const uint32_t sbase = smem_u32(smem);
    const __nv_bfloat16* srcs[4] = {Ah, Al, Bh, Bl};

    // prefetch stage s into buffer s&1 (2048 x 16B cp.async, 8/thread)
    auto prefetch = [&](int s) {
        const int k0 = s * KS;
        const uint32_t dst0 = sbase + (uint32_t)(s & 1) * STAGE_BYTES;
#pragma unroll
        for (int t = 0; t < 4; t++) {
            const __nv_bfloat16* sp = srcs[t];
            const int rb = (t < 2) ? m0 : n0;
#pragma unroll
            for (int i = 0; i < 2; i++) {
                int idx = tid + i * 256;          // 0..511
                int row = idx >> 2, c = idx & 3;
                const void* gsrc = sp + (size_t)(rb + row) * DD + k0 + c * 8;
                uint32_t sdst = dst0 + t * TILE_BYTES + row * (SS * 2) + c * 16;
                CP_ASYNC16(sdst, gsrc);
            }
        }
        CP_COMMIT();
    };

    float acc[4][4][4];
#pragma unroll
    for (int i = 0; i < 4; i++)
#pragma unroll
        for (int j = 0; j < 4; j++)
#pragma unroll
            for (int c = 0; c < 4; c++) acc[i][j][c] = 0.f;

    prefetch(0);
    for (int s = 0; s < DD / KS; s++) {
        CP_WAIT0();
        __syncthreads();
        if (s + 1 < DD / KS) prefetch(s + 1);

        const char* bufp = smem + (s & 1) * STAGE_BYTES;
        const char* pAh = bufp;
        const char* pAl = bufp + TILE_BYTES;
        const char* pBh = bufp + 2 * TILE_BYTES;
        const char* pBl = bufp + 3 * TILE_BYTES;

#pragma unroll
        for (int ks = 0; ks < 2; ks++) {
            const int kb = ks * 16;
            uint32_t ah[4][4], al[4][4], bh[4][2], bl[4][2];
#pragma unroll
            for (int i = 0; i < 4; i++) {
                int r = wm + i * 16 + g;
                int o0 = (r * SS + kb + 2 * tg) * 2;
                int o1 = ((r + 8) * SS + kb + 2 * tg) * 2;
                ah[i][0] = *(const uint32_t*)(pAh + o0);
                ah[i][1] = *(const uint32_t*)(pAh + o1);
                ah[i][2] = *(const uint32_t*)(pAh + o0 + 16);
                ah[i][3] = *(const uint32_t*)(pAh + o1 + 16);
                al[i][0] = *(const uint32_t*)(pAl + o0);
                al[i][1] = *(const uint32_t*)(pAl + o1);
                al[i][2] = *(const uint32_t*)(pAl + o0 + 16);
                al[i][3] = *(const uint32_t*)(pAl + o1 + 16);
            }
#pragma unroll
            for (int j = 0; j < 4; j++) {
                int r = wn + j * 8 + g;
                int o0 = (r * SS + kb + 2 * tg) * 2;
                bh[j][0] = *(const uint32_t*)(pBh + o0);
                bh[j][1] = *(const uint32_t*)(pBh + o0 + 16);
                bl[j][0] = *(const uint32_t*)(pBl + o0);
                bl[j][1] = *(const uint32_t*)(pBl + o0 + 16);
            }
#pragma unroll
            for (int i = 0; i < 4; i++)
#pragma unroll
                for (int j = 0; j < 4; j++) {
                    mma16816(acc[i][j], ah[i], bh[j]);
                    mma16816(acc[i][j], ah[i], bl[j]);
                    mma16816(acc[i][j], al[i], bh[j]);
                }
        }
    }

    // epilogue
#pragma unroll
    for (int i = 0; i < 4; i++) {
        int mA = m0 + wm + i * 16 + g;
#pragma unroll
        for (int j = 0; j < 4; j++) {
            int c = n0 + wn + j * 8 + 2 * tg;
            if (MODE == 0) {
                *(float2*)(out + (size_t)mA * DD + c) =
                    make_float2(acc[i][j][0], acc[i][j][1]);
                *(float2*)(out + (size_t)(mA + 8) * DD + c) =
                    make_float2(acc[i][j][2], acc[i][j][3]);
            } else {
                int h = c >> 6, t = c & 63;
                int b1 = mA >> 10, n1 = mA & 1023;
                int b2 = (mA + 8) >> 10, n2 = (mA + 8) & 1023;
                *(float2*)(out + ((size_t)(b1 * HH + h) * NN + n1) * HD + t) =
                    make_float2(acc[i][j][0], acc[i][j][1]);
                *(float2*)(out + ((size_t)(b2 * HH + h) * NN + n2) * HD + t) =
                    make_float2(acc[i][j][2], acc[i][j][3]);
            }
        }
    }
}

// ---------------- attention (fp32 SIMT, unchanged) ----------------
__global__ __launch_bounds__(256) void attn_kernel(const float* __restrict__ bias,
                                                   float* __restrict__ out)
{
    extern __shared__ float sm[];
    float* ps  = sm;
    float* sQ  = sm + 32*1024;
    float* sKV = sQ + 32*65;

    const int bh   = blockIdx.x;
    const int row0 = blockIdx.y * 32;
    const int tid  = threadIdx.x;
    const int tx = tid & 15, ty = tid >> 4;
    const int r0 = ty*2, r1 = ty*2 + 1;

    const float* q    = g_q + (size_t)bh*NN*HD + (size_t)row0*HD;
    const float* kptr = g_k + (size_t)bh*NN*HD;
    const float* vptr = g_v + (size_t)bh*NN*HD;
    const float* brow = bias + (size_t)bh*NN*NN + (size_t)row0*NN;

    for (int idx = tid; idx < 32*64; idx += 256)
        sQ[(idx >> 6)*65 + (idx & 63)] = q[idx];

    const float scale = 0.125f;

    for (int kc = 0; kc < 16; kc++) {
        __syncthreads();
        for (int idx = tid; idx < 64*64; idx += 256) {
            int kl = idx >> 6, d = idx & 63;
            sKV[d*68 + kl] = kptr[(size_t)kc*4096 + idx];
        }
        __syncthreads();
        float c0[4] = {}, c1[4] = {};
#pragma unroll 16
        for (int d = 0; d < 64; d++) {
            float a0 = sQ[r0*65 + d];
            float a1 = sQ[r1*65 + d];
            float4 b = *(const float4*)&sKV[d*68 + tx*4];
            c0[0] += a0*b.x; c0[1] += a0*b.y; c0[2] += a0*b.z; c0[3] += a0*b.w;
            c1[0] += a1*b.x; c1[1] += a1*b.y; c1[2] += a1*b.z; c1[3] += a1*b.w;
        }
        int key = kc*64 + tx*4;
        float4 bi0 = *(const float4*)&brow[(size_t)r0*NN + key];
        float4 bi1 = *(const float4*)&brow[(size_t)r1*NN + key];
        float4 s0 = make_float4(fmaf(c0[0], scale, bi0.x), fmaf(c0[1], scale, bi0.y),
                                fmaf(c0[2], scale, bi0.z), fmaf(c0[3], scale, bi0.w));
        float4 s1 = make_float4(fmaf(c1[0], scale, bi1.x), fmaf(c1[1], scale, bi1.y),
                                fmaf(c1[2], scale, bi1.z), fmaf(c1[3], scale, bi1.w));
        *(float4*)&ps[r0*1024 + key] = s0;
        *(float4*)&ps[r1*1024 + key] = s1;
    }
    __syncthreads();

    const int warp = tid >> 5, lane = tid & 31;
    for (int r = warp; r < 32; r += 8) {
        float* prow = ps + r*1024;
        float mx = -INFINITY;
        for (int i = lane; i < 1024; i += 32) mx = fmaxf(mx, prow[i]);
#pragma unroll
        for (int o = 16; o > 0; o >>= 1) mx = fmaxf(mx, __shfl_xor_sync(0xffffffffu, mx, o));
        float s = 0.f;
        for (int i = lane; i < 1024; i += 32) {
            float e = __expf(prow[i] - mx);
            prow[i] = e;
            s += e;
        }
#pragma unroll
        for (int o = 16; o > 0; o >>= 1) s += __shfl_xor_sync(0xffffffffu, s, o);
        float inv = 1.0f / s;
        for (int i = lane; i < 1024; i += 32) prow[i] *= inv;
    }

    float o0[4] = {}, o1[4] = {};
    for (int kc = 0; kc < 16; kc++) {
        __syncthreads();
        for (int idx = tid; idx < 64*64; idx += 256) {
            int kl = idx >> 6, t = idx & 63;
            sKV[kl*68 + t] = vptr[(size_t)kc*4096 + idx];
        }
        __syncthreads();
#pragma unroll 16
        for (int kk = 0; kk < 64; kk++) {
            float p0 = ps[r0*1024 + kc*64 + kk];
            float p1 = ps[r1*1024 + kc*64 + kk];
            float4 b = *(const float4*)&sKV[kk*68 + tx*4];
            o0[0] += p0*b.x; o0[1] += p0*b.y; o0[2] += p0*b.z; o0[3] += p0*b.w;
            o1[0] += p1*b.x; o1[1] += p1*b.y; o1[2] += p1*b.z; o1[3] += p1*b.w;
        }
    }

    int b = bh >> 4, h = bh & 15;
    float* op = out + (size_t)(b*NN + row0)*DD + h*HD + tx*4;
    *(float4*)&op[(size_t)r0*DD] = make_float4(o0[0], o0[1], o0[2], o0[3]);
    *(float4*)&op[(size_t)r1*DD] = make_float4(o1[0], o1[1], o1[2], o1[3]);
}

// ---------------- launch ----------------
extern "C" void kernel_launch(void* const* d_in, const int* in_sizes, int n_in,
                              void* d_out, int out_size)
{
    const float* x    = (const float*)d_in[0];
    const float* bias = (const float*)d_in[1];
    const float* W[4] = {(const float*)d_in[2], (const float*)d_in[3],
                         (const float*)d_in[4], (const float*)d_in[5]};
    float* out = (float*)d_out;

    float *qb, *kb, *vb, *ob;
    cudaGetSymbolAddress((void**)&qb, g_q);
    cudaGetSymbolAddress((void**)&kb, g_k);
    cudaGetSymbolAddress((void**)&vb, g_v);
    cudaGetSymbolAddress((void**)&ob, g_o);
    __nv_bfloat16 *xh, *xl, *oh, *ol, *wh, *wl;
    cudaGetSymbolAddress((void**)&xh, g_xh);
    cudaGetSymbolAddress((void**)&xl, g_xl);
    cudaGetSymbolAddress((void**)&oh, g_oh);
    cudaGetSymbolAddress((void**)&ol, g_ol);
    cudaGetSymbolAddress((void**)&wh, g_wh);
    cudaGetSymbolAddress((void**)&wl, g_wl);

    const int ATTN_SMEM = (32*1024 + 32*65 + 64*68) * 4;
    cudaFuncSetAttribute(attn_kernel, cudaFuncAttributeMaxDynamicSharedMemorySize, ATTN_SMEM);
    cudaFuncSetAttribute(gemm_mma<0>, cudaFuncAttributeMaxDynamicSharedMemorySize, GSMEM_BYTES);
    cudaFuncSetAttribute(gemm_mma<1>, cudaFuncAttributeMaxDynamicSharedMemorySize, GSMEM_BYTES);

    const int NX = BB*NN*DD;
    const int NW = DD*DD;

    split_kernel<<<NX/256, 256>>>(x, xh, xl, NX);
    for (int i = 0; i < 4; i++)
        split_kernel<<<NW/256, 256>>>(W[i], wh + (size_t)i*NW, wl + (size_t)i*NW, NW);

    dim3 gg(DD/128, (BB*NN)/128);   // (8, 32)
    gemm_mma<1><<<gg, 256, GSMEM_BYTES>>>(xh, xl, wh + 0*(size_t)NW, wl + 0*(size_t)NW, qb);
    gemm_mma<1><<<gg, 256, GSMEM_BYTES>>>(xh, xl, wh + 1*(size_t)NW, wl + 1*(size_t)NW, kb);
    gemm_mma<1><<<gg, 256, GSMEM_BYTES>>>(xh, xl, wh + 2*(size_t)NW, wl + 2*(size_t)NW, vb);

    attn_kernel<<<dim3(BH, NN/32), 256, ATTN_SMEM>>>(bias, ob);

    split_kernel<<<NX/256, 256>>>(ob, oh, ol, NX);
    gemm_mma<0><<<gg, 256, GSMEM_BYTES>>>(oh, ol, wh + 3*(size_t)NW, wl + 3*(size_t)NW, out);
}

// round 8
// speedup vs baseline: 3.5268x; 2.6154x over previous
#include <cuda_runtime.h>
#include <cuda_bf16.h>
#include <math.h>
#include <stdint.h>

#define BB 4
#define NN 1024
#define DD 1024
#define HH 16
#define HD 64
#define BH (BB*HH)

// ---------------- scratch (device globals; allocation-free) ----------------
__device__ __nv_bfloat16 g_xh[BB*NN*DD];
__device__ __nv_bfloat16 g_xl[BB*NN*DD];
__device__ __nv_bfloat16 g_wh[4][DD*DD];
__device__ __nv_bfloat16 g_wl[4][DD*DD];

__device__ __nv_bfloat16 g_qh[BH*NN*HD];   // [bh][n][hd], pre-scaled by 0.125
__device__ __nv_bfloat16 g_ql[BH*NN*HD];
__device__ __nv_bfloat16 g_kh[BH*NN*HD];
__device__ __nv_bfloat16 g_kl[BH*NN*HD];
__device__ __nv_bfloat16 g_vh[BH*NN*HD];
__device__ __nv_bfloat16 g_vl[BH*NN*HD];

__device__ __nv_bfloat16 g_oh[BB*NN*DD];   // attention out [B,N,D] hi/lo
__device__ __nv_bfloat16 g_ol[BB*NN*DD];

// ---------------- helpers ----------------
__device__ __forceinline__ uint32_t smem_u32(const void* p) {
    uint32_t a;
    asm("{ .reg .u64 t; cvta.to.shared.u64 t, %1; cvt.u32.u64 %0, t; }" : "=r"(a) : "l"(p));
    return a;
}
__device__ __forceinline__ void mma16816(float* d, const uint32_t* a, const uint32_t* b) {
    asm volatile(
        "mma.sync.aligned.m16n8k16.row.col.f32.bf16.bf16.f32 "
        "{%0,%1,%2,%3}, {%4,%5,%6,%7}, {%8,%9}, {%0,%1,%2,%3};"
        : "+f"(d[0]), "+f"(d[1]), "+f"(d[2]), "+f"(d[3])
        : "r"(a[0]), "r"(a[1]), "r"(a[2]), "r"(a[3]), "r"(b[0]), "r"(b[1]));
}
__device__ __forceinline__ void ldsm_x4(uint32_t* r, uint32_t addr) {
    asm volatile("ldmatrix.sync.aligned.m8n8.x4.shared.b16 {%0,%1,%2,%3}, [%4];"
        : "=r"(r[0]), "=r"(r[1]), "=r"(r[2]), "=r"(r[3]) : "r"(addr));
}
__device__ __forceinline__ void ldsm_x4_t(uint32_t* r, uint32_t addr) {
    asm volatile("ldmatrix.sync.aligned.m8n8.x4.trans.shared.b16 {%0,%1,%2,%3}, [%4];"
        : "=r"(r[0]), "=r"(r[1]), "=r"(r[2]), "=r"(r[3]) : "r"(addr));
}
#define CP_ASYNC16(sdst, gsrc) \
    asm volatile("cp.async.cg.shared.global [%0], [%1], 16;" :: "r"(sdst), "l"(gsrc))
#define CP_COMMIT() asm volatile("cp.async.commit_group;" ::: "memory")
#define CP_WAIT0()  asm volatile("cp.async.wait_group 0;" ::: "memory")

__device__ __forceinline__ void packsplit(float f0, float f1, uint32_t& hi, uint32_t& lo) {
    __nv_bfloat162 h = __floats2bfloat162_rn(f0, f1);
    float r0 = f0 - __bfloat162float(h.x);
    float r1 = f1 - __bfloat162float(h.y);
    __nv_bfloat162 l = __floats2bfloat162_rn(r0, r1);
    hi = *reinterpret_cast<uint32_t*>(&h);
    lo = *reinterpret_cast<uint32_t*>(&l);
}

// ---------------- fp32 -> bf16 hi/lo split ----------------
__global__ __launch_bounds__(256) void split_kernel(const float* __restrict__ s,
                                                    __nv_bfloat16* __restrict__ h,
                                                    __nv_bfloat16* __restrict__ l, int n)
{
    int i = blockIdx.x * 256 + threadIdx.x;
    if (i < n) {
        float v = s[i];
        __nv_bfloat16 hh = __float2bfloat16(v);
        h[i] = hh;
        l[i] = __float2bfloat16(v - __bfloat162float(hh));
    }
}

// ---------------- split-bf16 GEMM (HMMA + ldmatrix) ----------------
// C[M,N] = A[M,K] @ B[N,K]^T, 3-term split, 128x128 CTA tile, 8 warps 64x32.
// MODE0: fp32 out[m*1024+n].  MODE1: bf16 hi/lo head-scatter, acc*scl.
#define KS 32
#define SS 40
#define RB (SS*2)                      // 80 bytes/row
#define TILE_BYTES (128*RB)            // 10240
#define STAGE_BYTES (4*TILE_BYTES)
#define GSMEM_BYTES (2*STAGE_BYTES)

template<int MODE>
__global__ __launch_bounds__(256) void gemm_mma(
    const __nv_bfloat16* __restrict__ Ah, const __nv_bfloat16* __restrict__ Al,
    const __nv_bfloat16* __restrict__ Bh, const __nv_bfloat16* __restrict__ Bl,
    float* __restrict__ outF, __nv_bfloat16* __restrict__ outH,
    __nv_bfloat16* __restrict__ outL, float scl)
{
    extern __shared__ __align__(16) char smem[];
    const int tid = threadIdx.x;
    const int wid = tid >> 5, lane = tid & 31;
    const int g = lane >> 2, tg = lane & 3;
    const int m0 = blockIdx.y * 128, n0 = blockIdx.x * 128;
    const int wm = (wid & 1) * 64, wn = (wid >> 1) * 32;

    const uint32_t sbase = smem_u32(smem);
    const __nv_bfloat16* srcs[4] = {Ah, Al, Bh, Bl};

    auto prefetch = [&](int s) {
        const int k0 = s * KS;
        const uint32_t dst0 = sbase + (uint32_t)(s & 1) * STAGE_BYTES;
#pragma unroll
        for (int t = 0; t < 4; t++) {
            const __nv_bfloat16* sp = srcs[t];
            const int rb = (t < 2) ? m0 : n0;
#pragma unroll
            for (int i = 0; i < 2; i++) {
                int idx = tid + i * 256;
                int row = idx >> 2, c = idx & 3;
                const void* gsrc = sp + (size_t)(rb + row) * DD + k0 + c * 8;
                CP_ASYNC16(dst0 + t * TILE_BYTES + row * RB + c * 16, gsrc);
            }
        }
        CP_COMMIT();
    };

    float acc[4][4][4];
#pragma unroll
    for (int i = 0; i < 4; i++)
#pragma unroll
        for (int j = 0; j < 4; j++)
#pragma unroll
            for (int c = 0; c < 4; c++) acc[i][j][c] = 0.f;

    // ldmatrix per-lane byte offsets
    const uint32_t laneA = (lane & 15) * RB + (lane >> 4) * 16;
    const uint32_t laneB = ((lane & 7) + (lane >> 4) * 8) * RB + ((lane >> 3) & 1) * 16;

    prefetch(0);
    for (int s = 0; s < DD / KS; s++) {
        CP_WAIT0();
        __syncthreads();
        if (s + 1 < DD / KS) prefetch(s + 1);
        const uint32_t st = sbase + (uint32_t)(s & 1) * STAGE_BYTES;

#pragma unroll
        for (int ks = 0; ks < 2; ks++) {
            const int kb2 = ks * 32;   // kb*2 bytes
            uint32_t ah[4][4], al[4][4], bh[8], bl[8];
#pragma unroll
            for (int i = 0; i < 4; i++) {
                uint32_t aA = st + (wm + 16 * i) * RB + kb2 + laneA;
                ldsm_x4(ah[i], aA);
                ldsm_x4(al[i], aA + TILE_BYTES);
            }
            {
                uint32_t b0 = st + 2 * TILE_BYTES + wn * RB + kb2 + laneB;
                ldsm_x4(bh,     b0);
                ldsm_x4(bh + 4, b0 + 16 * RB);
                ldsm_x4(bl,     b0 + TILE_BYTES);
                ldsm_x4(bl + 4, b0 + TILE_BYTES + 16 * RB);
            }
#pragma unroll
            for (int i = 0; i < 4; i++)
#pragma unroll
                for (int j = 0; j < 4; j++) {
                    mma16816(acc[i][j], ah[i], bh + 2 * j);
                    mma16816(acc[i][j], ah[i], bl + 2 * j);
                    mma16816(acc[i][j], al[i], bh + 2 * j);
                }
        }
    }

#pragma unroll
    for (int i = 0; i < 4; i++) {
        int mA = m0 + wm + i * 16 + g;
#pragma unroll
        for (int j = 0; j < 4; j++) {
            int c = n0 + wn + j * 8 + 2 * tg;
            if (MODE == 0) {
                *(float2*)(outF + (size_t)mA * DD + c) =
                    make_float2(acc[i][j][0], acc[i][j][1]);
                *(float2*)(outF + (size_t)(mA + 8) * DD + c) =
                    make_float2(acc[i][j][2], acc[i][j][3]);
            } else {
                int h = c >> 6, t = c & 63;
                int b1 = mA >> 10, n1 = mA & 1023;
                int b2 = (mA + 8) >> 10, n2 = (mA + 8) & 1023;
                size_t i1 = ((size_t)(b1 * HH + h) * NN + n1) * HD + t;
                size_t i2 = ((size_t)(b2 * HH + h) * NN + n2) * HD + t;
                uint32_t hi, lo;
                packsplit(acc[i][j][0] * scl, acc[i][j][1] * scl, hi, lo);
                *(uint32_t*)(outH + i1) = hi;
                *(uint32_t*)(outL + i1) = lo;
                packsplit(acc[i][j][2] * scl, acc[i][j][3] * scl, hi, lo);
                *(uint32_t*)(outH + i2) = hi;
                *(uint32_t*)(outL + i2) = lo;
            }
        }
    }
}

// ---------------- flash attention on HMMA (split bf16) ----------------
// CTA: one (b,h) x 128 q rows. 8 warps x 16 rows. KV chunks of 128 keys, double buffered.
#define ATS 72
#define ATSB (ATS*2)                   // 144 bytes/row
#define ATILE (128*ATSB)               // 18432
#define AKV_STAGE (4*ATILE)            // 73728
#define ASMEM (2*ATILE + 2*AKV_STAGE)  // 184320

__global__ __launch_bounds__(256) void attn_mma(const float* __restrict__ bias)
{
    extern __shared__ __align__(16) char smem[];
    const int tid = threadIdx.x, wid = tid >> 5, lane = tid & 31;
    const int g = lane >> 2, tg = lane & 3;
    const int bh = blockIdx.x;
    const int row0 = blockIdx.y * 128;
    const int wq = wid * 16;
    const uint32_t sb = smem_u32(smem);

    const __nv_bfloat16* qhp = g_qh + (size_t)bh * NN * HD;
    const __nv_bfloat16* qlp = g_ql + (size_t)bh * NN * HD;
    const __nv_bfloat16* khp = g_kh + (size_t)bh * NN * HD;
    const __nv_bfloat16* klp = g_kl + (size_t)bh * NN * HD;
    const __nv_bfloat16* vhp = g_vh + (size_t)bh * NN * HD;
    const __nv_bfloat16* vlp = g_vl + (size_t)bh * NN * HD;

    auto issue_kv = [&](int c) {
        const uint32_t stg = sb + 2 * ATILE + (uint32_t)(c & 1) * AKV_STAGE;
#pragma unroll
        for (int i = 0; i < 4; i++) {
            int idx = tid + i * 256;
            int row = idx >> 3, ch = idx & 7;
            size_t go = (size_t)(c * 128 + row) * HD + ch * 8;
            uint32_t dst = stg + row * ATSB + ch * 16;
            CP_ASYNC16(dst,             khp + go);
            CP_ASYNC16(dst + ATILE,     klp + go);
            CP_ASYNC16(dst + 2 * ATILE, vhp + go);
            CP_ASYNC16(dst + 3 * ATILE, vlp + go);
        }
    };

    // Q tile + first KV stage in one group
#pragma unroll
    for (int i = 0; i < 4; i++) {
        int idx = tid + i * 256;
        int row = idx >> 3, ch = idx & 7;
        size_t go = (size_t)(row0 + row) * HD + ch * 8;
        uint32_t dst = sb + row * ATSB + ch * 16;
        CP_ASYNC16(dst,         qhp + go);
        CP_ASYNC16(dst + ATILE, qlp + go);
    }
    issue_kv(0);
    CP_COMMIT();

    float sA[16][4];
    float O[8][4];
#pragma unroll
    for (int j = 0; j < 8; j++)
#pragma unroll
        for (int c = 0; c < 4; c++) O[j][c] = 0.f;
    float mo[2] = {-1e30f, -1e30f}, ls[2] = {0.f, 0.f};
    uint32_t qfh[4][4], qfl[4][4];

    const float* biasP = bias + ((size_t)bh * NN + row0 + wq + g) * NN + 2 * tg;

    const uint32_t laneQ = (lane & 15) * ATSB + (lane >> 4) * 16;
    const uint32_t laneK = (lane & 7) * ATSB + (lane >> 3) * 16;
    const uint32_t laneV = ((lane & 7) + ((lane >> 3) & 1) * 8) * ATSB + (lane >> 4) * 16;

    for (int c = 0; c < 8; c++) {
        CP_WAIT0();
        __syncthreads();
        if (c == 0) {
#pragma unroll
            for (int t = 0; t < 4; t++) {
                uint32_t qa = sb + wq * ATSB + t * 32 + laneQ;
                ldsm_x4(qfh[t], qa);
                ldsm_x4(qfl[t], qa + ATILE);
            }
        }
        if (c + 1 < 8) { issue_kv(c + 1); CP_COMMIT(); }

        const uint32_t kh_b = sb + 2 * ATILE + (uint32_t)(c & 1) * AKV_STAGE;

        // ---- S = bias + Q K^T ----
        const float* bp = biasP + c * 128;
#pragma unroll
        for (int j = 0; j < 16; j++) {
            float2 u = *(const float2*)(bp + 8 * j);
            float2 w = *(const float2*)(bp + 8 * NN + 8 * j);
            sA[j][0] = u.x; sA[j][1] = u.y; sA[j][2] = w.x; sA[j][3] = w.y;
        }
#pragma unroll 4
        for (int j = 0; j < 16; j++) {
            uint32_t kh[8], kl[8];
            uint32_t ka = kh_b + j * 8 * ATSB + laneK;
            ldsm_x4(kh,     ka);
            ldsm_x4(kh + 4, ka + 64);
            ldsm_x4(kl,     ka + ATILE);
            ldsm_x4(kl + 4, ka + ATILE + 64);
#pragma unroll
            for (int t = 0; t < 4; t++) {
                mma16816(sA[j], qfh[t], kh + 2 * t);
                mma16816(sA[j], qfh[t], kl + 2 * t);
                mma16816(sA[j], qfl[t], kh + 2 * t);
            }
        }

        // ---- online softmax (per-lane rows g, g+8) ----
#pragma unroll
        for (int h = 0; h < 2; h++) {
            float mx = -1e30f;
#pragma unroll
            for (int j = 0; j < 16; j++)
                mx = fmaxf(mx, fmaxf(sA[j][2 * h], sA[j][2 * h + 1]));
            mx = fmaxf(mx, __shfl_xor_sync(0xffffffffu, mx, 1));
            mx = fmaxf(mx, __shfl_xor_sync(0xffffffffu, mx, 2));
            float mn = fmaxf(mo[h], mx);
            float al = __expf(mo[h] - mn);
            mo[h] = mn;
            float ps = 0.f;
#pragma unroll
            for (int j = 0; j < 16; j++) {
                float e0 = __expf(sA[j][2 * h] - mn);
                float e1 = __expf(sA[j][2 * h + 1] - mn);
                sA[j][2 * h] = e0; sA[j][2 * h + 1] = e1;
                ps += e0 + e1;
            }
            ls[h] = ls[h] * al + ps;
#pragma unroll
            for (int jo = 0; jo < 8; jo++) {
                O[jo][2 * h] *= al;
                O[jo][2 * h + 1] *= al;
            }
        }

        // ---- O += P V ----
        const uint32_t vh_b = kh_b + 2 * ATILE;
#pragma unroll 2
        for (int t = 0; t < 8; t++) {
            uint32_t aph[4], apl[4];
            packsplit(sA[2 * t][0],     sA[2 * t][1],     aph[0], apl[0]);
            packsplit(sA[2 * t][2],     sA[2 * t][3],     aph[1], apl[1]);
            packsplit(sA[2 * t + 1][0], sA[2 * t + 1][1], aph[2], apl[2]);
            packsplit(sA[2 * t + 1][2], sA[2 * t + 1][3], aph[3], apl[3]);
#pragma unroll
            for (int jp = 0; jp < 8; jp += 2) {
                uint32_t vh[4], vl[4];
                uint32_t va = vh_b + t * 16 * ATSB + jp * 16 + laneV;
                ldsm_x4_t(vh, va);
                ldsm_x4_t(vl, va + ATILE);
                mma16816(O[jp],     aph, vh);
                mma16816(O[jp],     aph, vl);
                mma16816(O[jp],     apl, vh);
                mma16816(O[jp + 1], aph, vh + 2);
                mma16816(O[jp + 1], aph, vl + 2);
                mma16816(O[jp + 1], apl, vh + 2);
            }
        }
    }

    // ---- finalize: divide by row sums, write hi/lo bf16 [B,N,D] ----
    float inv[2];
#pragma unroll
    for (int h = 0; h < 2; h++) {
        float v = ls[h];
        v += __shfl_xor_sync(0xffffffffu, v, 1);
        v += __shfl_xor_sync(0xffffffffu, v, 2);
        inv[h] = 1.0f / v;
    }
    const int b = bh >> 4, hh = bh & 15;
    const size_t r1 = ((size_t)(b * NN + row0 + wq + g)) * DD + hh * HD + 2 * tg;
    const size_t r2 = r1 + (size_t)8 * DD;
#pragma unroll
    for (int jo = 0; jo < 8; jo++) {
        uint32_t hi, lo;
        packsplit(O[jo][0] * inv[0], O[jo][1] * inv[0], hi, lo);
        *(uint32_t*)(g_oh + r1 + 8 * jo) = hi;
        *(uint32_t*)(g_ol + r1 + 8 * jo) = lo;
        packsplit(O[jo][2] * inv[1], O[jo][3] * inv[1], hi, lo);
        *(uint32_t*)(g_oh + r2 + 8 * jo) = hi;
        *(uint32_t*)(g_ol + r2 + 8 * jo) = lo;
    }
}

// ---------------- launch ----------------
extern "C" void kernel_launch(void* const* d_in, const int* in_sizes, int n_in,
                              void* d_out, int out_size)
{
    const float* x    = (const float*)d_in[0];
    const float* bias = (const float*)d_in[1];
    const float* W[4] = {(const float*)d_in[2], (const float*)d_in[3],
                         (const float*)d_in[4], (const float*)d_in[5]};
    float* out = (float*)d_out;

    __nv_bfloat16 *xh, *xl, *wh, *wl, *qh, *ql, *kh, *kl, *vh, *vl, *oh, *ol;
    cudaGetSymbolAddress((void**)&xh, g_xh);
    cudaGetSymbolAddress((void**)&xl, g_xl);
    cudaGetSymbolAddress((void**)&wh, g_wh);
    cudaGetSymbolAddress((void**)&wl, g_wl);
    cudaGetSymbolAddress((void**)&qh, g_qh);
    cudaGetSymbolAddress((void**)&ql, g_ql);
    cudaGetSymbolAddress((void**)&kh, g_kh);
    cudaGetSymbolAddress((void**)&kl, g_kl);
    cudaGetSymbolAddress((void**)&vh, g_vh);
    cudaGetSymbolAddress((void**)&vl, g_vl);
    cudaGetSymbolAddress((void**)&oh, g_oh);
    cudaGetSymbolAddress((void**)&ol, g_ol);

    cudaFuncSetAttribute(gemm_mma<0>, cudaFuncAttributeMaxDynamicSharedMemorySize, GSMEM_BYTES);
    cudaFuncSetAttribute(gemm_mma<1>, cudaFuncAttributeMaxDynamicSharedMemorySize, GSMEM_BYTES);
    cudaFuncSetAttribute(attn_mma, cudaFuncAttributeMaxDynamicSharedMemorySize, ASMEM);

    const int NX = BB*NN*DD;
    const int NW = DD*DD;

    split_kernel<<<NX/256, 256>>>(x, xh, xl, NX);
    for (int i = 0; i < 4; i++)
        split_kernel<<<NW/256, 256>>>(W[i], wh + (size_t)i*NW, wl + (size_t)i*NW, NW);

    dim3 gg(DD/128, (BB*NN)/128);   // (8, 32)
    // Q pre-scaled by hd^-0.5 = 0.125 (exact power of 2)
    gemm_mma<1><<<gg, 256, GSMEM_BYTES>>>(xh, xl, wh + 0*(size_t)NW, wl + 0*(size_t)NW,
                                          nullptr, qh, ql, 0.125f);
    gemm_mma<1><<<gg, 256, GSMEM_BYTES>>>(xh, xl, wh + 1*(size_t)NW, wl + 1*(size_t)NW,
                                          nullptr, kh, kl, 1.0f);
    gemm_mma<1><<<gg, 256, GSMEM_BYTES>>>(xh, xl, wh + 2*(size_t)NW, wl + 2*(size_t)NW,
                                          nullptr, vh, vl, 1.0f);

    attn_mma<<<dim3(BH, NN/128), 256, ASMEM>>>(bias);

    gemm_mma<0><<<gg, 256, GSMEM_BYTES>>>(oh, ol, wh + 3*(size_t)NW, wl + 3*(size_t)NW,
                                          out, nullptr, nullptr, 1.0f);
}

// round 9
// speedup vs baseline: 4.4315x; 1.2565x over previous
#include <cuda_runtime.h>
#include <cuda_fp16.h>
#include <math.h>
#include <stdint.h>

#define BB 4
#define NN 1024
#define DD 1024
#define HH 16
#define HD 64
#define BH (BB*HH)

// ---------------- scratch (device globals; allocation-free) ----------------
__device__ __half g_xh[BB*NN*DD];      // x hi
__device__ __half g_xl[BB*NN*DD];      // x lo
__device__ __half g_w[4][DD*DD];       // Wq,Wk,Wv,Wo rounded to fp16 (single)

__device__ __half g_qh[BH*NN*HD];      // Q hi (pre-scaled by 0.125)
__device__ __half g_ql[BH*NN*HD];      // Q lo
__device__ __half g_k [BH*NN*HD];      // K single
__device__ __half g_v [BH*NN*HD];      // V single

__device__ __half g_oh[BB*NN*DD];      // attention out hi [B,N,D]
__device__ __half g_ol[BB*NN*DD];      // attention out lo

// ---------------- helpers ----------------
__device__ __forceinline__ uint32_t smem_u32(const void* p) {
    uint32_t a;
    asm("{ .reg .u64 t; cvta.to.shared.u64 t, %1; cvt.u32.u64 %0, t; }" : "=r"(a) : "l"(p));
    return a;
}
__device__ __forceinline__ void mma16816(float* d, const uint32_t* a, const uint32_t* b) {
    asm volatile(
        "mma.sync.aligned.m16n8k16.row.col.f32.f16.f16.f32 "
        "{%0,%1,%2,%3}, {%4,%5,%6,%7}, {%8,%9}, {%0,%1,%2,%3};"
        : "+f"(d[0]), "+f"(d[1]), "+f"(d[2]), "+f"(d[3])
        : "r"(a[0]), "r"(a[1]), "r"(a[2]), "r"(a[3]), "r"(b[0]), "r"(b[1]));
}
__device__ __forceinline__ void ldsm_x4(uint32_t* r, uint32_t addr) {
    asm volatile("ldmatrix.sync.aligned.m8n8.x4.shared.b16 {%0,%1,%2,%3}, [%4];"
        : "=r"(r[0]), "=r"(r[1]), "=r"(r[2]), "=r"(r[3]) : "r"(addr));
}
__device__ __forceinline__ void ldsm_x4_t(uint32_t* r, uint32_t addr) {
    asm volatile("ldmatrix.sync.aligned.m8n8.x4.trans.shared.b16 {%0,%1,%2,%3}, [%4];"
        : "=r"(r[0]), "=r"(r[1]), "=r"(r[2]), "=r"(r[3]) : "r"(addr));
}
#define CP_ASYNC16(sdst, gsrc) \
    asm volatile("cp.async.cg.shared.global [%0], [%1], 16;" :: "r"(sdst), "l"(gsrc))
#define CP_COMMIT() asm volatile("cp.async.commit_group;" ::: "memory")
#define CP_WAIT0()  asm volatile("cp.async.wait_group 0;" ::: "memory")

__device__ __forceinline__ void packsplit_h(float f0, float f1, uint32_t& hi, uint32_t& lo) {
    __half2 h = __floats2half2_rn(f0, f1);
    float r0 = f0 - __low2float(h);
    float r1 = f1 - __high2float(h);
    __half2 l = __floats2half2_rn(r0, r1);
    hi = *reinterpret_cast<uint32_t*>(&h);
    lo = *reinterpret_cast<uint32_t*>(&l);
}
__device__ __forceinline__ uint32_t pack_h(float f0, float f1) {
    __half2 h = __floats2half2_rn(f0, f1);
    return *reinterpret_cast<uint32_t*>(&h);
}

// ---------------- prep kernels ----------------
__global__ __launch_bounds__(256) void split_x_kernel(const float* __restrict__ s,
                                                      __half* __restrict__ h,
                                                      __half* __restrict__ l, int n2)
{
    int i = blockIdx.x * 256 + threadIdx.x;
    if (i < n2) {
        float2 v = ((const float2*)s)[i];
        uint32_t hi, lo;
        packsplit_h(v.x, v.y, hi, lo);
        ((uint32_t*)h)[i] = hi;
        ((uint32_t*)l)[i] = lo;
    }
}
__global__ __launch_bounds__(256) void round_w_kernel(const float* __restrict__ s,
                                                      __half* __restrict__ h, int n2)
{
    int i = blockIdx.x * 256 + threadIdx.x;
    if (i < n2) {
        float2 v = ((const float2*)s)[i];
        ((uint32_t*)h)[i] = pack_h(v.x, v.y);
    }
}

// ---------------- 2-term fp16 GEMM (HMMA + ldmatrix) ----------------
// C[M,N] = (Ah+Al)[M,K] @ B[N,K]^T. CTA 128x128, 8 warps 64x32, K-stage 32.
// MODE0: fp32 out[m*1024+n]
// MODE1: head-scatter, split hi/lo fp16, acc*scl
// MODE2: head-scatter, single fp16
#define KS 32
#define SS 40
#define RB (SS*2)                      // 80 bytes/row
#define TILE_BYTES (128*RB)            // 10240
#define STAGE_BYTES (3*TILE_BYTES)     // 30720: Ah, Al, B
#define GSMEM_BYTES (2*STAGE_BYTES)    // 61440

template<int MODE>
__global__ __launch_bounds__(256) void gemm_mma(
    const __half* __restrict__ Ah, const __half* __restrict__ Al,
    const __half* __restrict__ Bw,
    float* __restrict__ outF, __half* __restrict__ outH,
    __half* __restrict__ outL, float scl)
{
    extern __shared__ __align__(16) char smem[];
    const int tid = threadIdx.x;
    const int wid = tid >> 5, lane = tid & 31;
    const int g = lane >> 2, tg = lane & 3;
    const int m0 = blockIdx.y * 128, n0 = blockIdx.x * 128;
    const int wm = (wid & 1) * 64, wn = (wid >> 1) * 32;

    const uint32_t sbase = smem_u32(smem);
    const __half* srcs[3] = {Ah, Al, Bw};

    auto prefetch = [&](int s) {
        const int k0 = s * KS;
        const uint32_t dst0 = sbase + (uint32_t)(s & 1) * STAGE_BYTES;
#pragma unroll
        for (int t = 0; t < 3; t++) {
            const __half* sp = srcs[t];
            const int rb = (t < 2) ? m0 : n0;
#pragma unroll
            for (int i = 0; i < 2; i++) {
                int idx = tid + i * 256;
                int row = idx >> 2, c = idx & 3;
                const void* gsrc = sp + (size_t)(rb + row) * DD + k0 + c * 8;
                CP_ASYNC16(dst0 + t * TILE_BYTES + row * RB + c * 16, gsrc);
            }
        }
        CP_COMMIT();
    };

    float acc[4][4][4];
#pragma unroll
    for (int i = 0; i < 4; i++)
#pragma unroll
        for (int j = 0; j < 4; j++)
#pragma unroll
            for (int c = 0; c < 4; c++) acc[i][j][c] = 0.f;

    const uint32_t laneA = (lane & 15) * RB + (lane >> 4) * 16;
    const uint32_t laneB = ((lane & 7) + (lane >> 4) * 8) * RB + ((lane >> 3) & 1) * 16;

    prefetch(0);
    for (int s = 0; s < DD / KS; s++) {
        CP_WAIT0();
        __syncthreads();
        if (s + 1 < DD / KS) prefetch(s + 1);
        const uint32_t st = sbase + (uint32_t)(s & 1) * STAGE_BYTES;

#pragma unroll
        for (int ks = 0; ks < 2; ks++) {
            const int kb2 = ks * 32;
            uint32_t ah[4][4], al[4][4], bh[8];
#pragma unroll
            for (int i = 0; i < 4; i++) {
                uint32_t aA = st + (wm + 16 * i) * RB + kb2 + laneA;
                ldsm_x4(ah[i], aA);
                ldsm_x4(al[i], aA + TILE_BYTES);
            }
            {
                uint32_t b0 = st + 2 * TILE_BYTES + wn * RB + kb2 + laneB;
                ldsm_x4(bh,     b0);
                ldsm_x4(bh + 4, b0 + 16 * RB);
            }
#pragma unroll
            for (int i = 0; i < 4; i++)
#pragma unroll
                for (int j = 0; j < 4; j++) {
                    mma16816(acc[i][j], ah[i], bh + 2 * j);
                    mma16816(acc[i][j], al[i], bh + 2 * j);
                }
        }
    }

#pragma unroll
    for (int i = 0; i < 4; i++) {
        int mA = m0 + wm + i * 16 + g;
#pragma unroll
        for (int j = 0; j < 4; j++) {
            int c = n0 + wn + j * 8 + 2 * tg;
            if (MODE == 0) {
                *(float2*)(outF + (size_t)mA * DD + c) =
                    make_float2(acc[i][j][0], acc[i][j][1]);
                *(float2*)(outF + (size_t)(mA + 8) * DD + c) =
                    make_float2(acc[i][j][2], acc[i][j][3]);
            } else {
                int h = c >> 6, t = c & 63;
                int b1 = mA >> 10, n1 = mA & 1023;
                int b2 = (mA + 8) >> 10, n2 = (mA + 8) & 1023;
                size_t i1 = ((size_t)(b1 * HH + h) * NN + n1) * HD + t;
                size_t i2 = ((size_t)(b2 * HH + h) * NN + n2) * HD + t;
                if (MODE == 1) {
                    uint32_t hi, lo;
                    packsplit_h(acc[i][j][0] * scl, acc[i][j][1] * scl, hi, lo);
                    *(uint32_t*)(outH + i1) = hi;
                    *(uint32_t*)(outL + i1) = lo;
                    packsplit_h(acc[i][j][2] * scl, acc[i][j][3] * scl, hi, lo);
                    *(uint32_t*)(outH + i2) = hi;
                    *(uint32_t*)(outL + i2) = lo;
                } else {
                    *(uint32_t*)(outH + i1) = pack_h(acc[i][j][0], acc[i][j][1]);
                    *(uint32_t*)(outH + i2) = pack_h(acc[i][j][2], acc[i][j][3]);
                }
            }
        }
    }
}

// ---------------- flash attention (fp16 2-term) ----------------
// CTA: one (b,h) x 128 q rows, 8 warps x 16 rows. KV chunks 128 keys, double buffered.
// Q split hi/lo (A-side); K, V single fp16 (B-side).
#define ATS 72
#define ATSB (ATS*2)                   // 144 bytes/row
#define ATILE (128*ATSB)               // 18432
#define AKV_STAGE (2*ATILE)            // 36864: K, V
#define ASMEM (2*ATILE + 2*AKV_STAGE)  // 110592

__global__ __launch_bounds__(256) void attn_mma(const float* __restrict__ bias)
{
    extern __shared__ __align__(16) char smem[];
    const int tid = threadIdx.x, wid = tid >> 5, lane = tid & 31;
    const int g = lane >> 2, tg = lane & 3;
    const int bh = blockIdx.x;
    const int row0 = blockIdx.y * 128;
    const int wq = wid * 16;
    const uint32_t sb = smem_u32(smem);

    const __half* qhp = g_qh + (size_t)bh * NN * HD;
    const __half* qlp = g_ql + (size_t)bh * NN * HD;
    const __half* kp  = g_k  + (size_t)bh * NN * HD;
    const __half* vp  = g_v  + (size_t)bh * NN * HD;

    auto issue_kv = [&](int c) {
        const uint32_t stg = sb + 2 * ATILE + (uint32_t)(c & 1) * AKV_STAGE;
#pragma unroll
        for (int i = 0; i < 4; i++) {
            int idx = tid + i * 256;
            int row = idx >> 3, ch = idx & 7;
            size_t go = (size_t)(c * 128 + row) * HD + ch * 8;
            uint32_t dst = stg + row * ATSB + ch * 16;
            CP_ASYNC16(dst,         kp + go);
            CP_ASYNC16(dst + ATILE, vp + go);
        }
    };

#pragma unroll
    for (int i = 0; i < 4; i++) {
        int idx = tid + i * 256;
        int row = idx >> 3, ch = idx & 7;
        size_t go = (size_t)(row0 + row) * HD + ch * 8;
        uint32_t dst = sb + row * ATSB + ch * 16;
        CP_ASYNC16(dst,         qhp + go);
        CP_ASYNC16(dst + ATILE, qlp + go);
    }
    issue_kv(0);
    CP_COMMIT();

    float sA[16][4];
    float O[8][4];
#pragma unroll
    for (int j = 0; j < 8; j++)
#pragma unroll
        for (int c = 0; c < 4; c++) O[j][c] = 0.f;
    float mo[2] = {-1e30f, -1e30f}, ls[2] = {0.f, 0.f};
    uint32_t qfh[4][4], qfl[4][4];

    const float* biasP = bias + ((size_t)bh * NN + row0 + wq + g) * NN + 2 * tg;

    const uint32_t laneQ = (lane & 15) * ATSB + (lane >> 4) * 16;
    const uint32_t laneK = (lane & 7) * ATSB + (lane >> 3) * 16;
    const uint32_t laneV = ((lane & 7) + ((lane >> 3) & 1) * 8) * ATSB + (lane >> 4) * 16;

    for (int c = 0; c < 8; c++) {
        CP_WAIT0();
        __syncthreads();
        if (c == 0) {
#pragma unroll
            for (int t = 0; t < 4; t++) {
                uint32_t qa = sb + wq * ATSB + t * 32 + laneQ;
                ldsm_x4(qfh[t], qa);
                ldsm_x4(qfl[t], qa + ATILE);
            }
        }
        if (c + 1 < 8) { issue_kv(c + 1); CP_COMMIT(); }

        const uint32_t kh_b = sb + 2 * ATILE + (uint32_t)(c & 1) * AKV_STAGE;

        // ---- S = bias + Q K^T ----
        const float* bp = biasP + c * 128;
#pragma unroll
        for (int j = 0; j < 16; j++) {
            float2 u = *(const float2*)(bp + 8 * j);
            float2 w = *(const float2*)(bp + 8 * NN + 8 * j);
            sA[j][0] = u.x; sA[j][1] = u.y; sA[j][2] = w.x; sA[j][3] = w.y;
        }
#pragma unroll 4
        for (int j = 0; j < 16; j++) {
            uint32_t kf[8];
            uint32_t ka = kh_b + j * 8 * ATSB + laneK;
            ldsm_x4(kf,     ka);
            ldsm_x4(kf + 4, ka + 64);
#pragma unroll
            for (int t = 0; t < 4; t++) {
                mma16816(sA[j], qfh[t], kf + 2 * t);
                mma16816(sA[j], qfl[t], kf + 2 * t);
            }
        }

        // ---- online softmax (per-lane rows g, g+8) ----
#pragma unroll
        for (int h = 0; h < 2; h++) {
            float mx = -1e30f;
#pragma unroll
            for (int j = 0; j < 16; j++)
                mx = fmaxf(mx, fmaxf(sA[j][2 * h], sA[j][2 * h + 1]));
            mx = fmaxf(mx, __shfl_xor_sync(0xffffffffu, mx, 1));
            mx = fmaxf(mx, __shfl_xor_sync(0xffffffffu, mx, 2));
            float mn = fmaxf(mo[h], mx);
            float al = __expf(mo[h] - mn);
            mo[h] = mn;
            float ps = 0.f;
#pragma unroll
            for (int j = 0; j < 16; j++) {
                float e0 = __expf(sA[j][2 * h] - mn);
                float e1 = __expf(sA[j][2 * h + 1] - mn);
                sA[j][2 * h] = e0; sA[j][2 * h + 1] = e1;
                ps += e0 + e1;
            }
            ls[h] = ls[h] * al + ps;
#pragma unroll
            for (int jo = 0; jo < 8; jo++) {
                O[jo][2 * h] *= al;
                O[jo][2 * h + 1] *= al;
            }
        }

        // ---- O += P V  (P split hi/lo, V single) ----
        const uint32_t vh_b = kh_b + ATILE;
#pragma unroll 2
        for (int t = 0; t < 8; t++) {
            uint32_t aph[4], apl[4];
            packsplit_h(sA[2 * t][0],     sA[2 * t][1],     aph[0], apl[0]);
            packsplit_h(sA[2 * t][2],     sA[2 * t][3],     aph[1], apl[1]);
            packsplit_h(sA[2 * t + 1][0], sA[2 * t + 1][1], aph[2], apl[2]);
            packsplit_h(sA[2 * t + 1][2], sA[2 * t + 1][3], aph[3], apl[3]);
#pragma unroll
            for (int jp = 0; jp < 8; jp += 2) {
                uint32_t vf[4];
                uint32_t va = vh_b + t * 16 * ATSB + jp * 16 + laneV;
                ldsm_x4_t(vf, va);
                mma16816(O[jp],     aph, vf);
                mma16816(O[jp],     apl, vf);
                mma16816(O[jp + 1], aph, vf + 2);
                mma16816(O[jp + 1], apl, vf + 2);
            }
        }
    }

    // ---- finalize: divide by row sums, write hi/lo fp16 [B,N,D] ----
    float inv[2];
#pragma unroll
    for (int h = 0; h < 2; h++) {
        float v = ls[h];
        v += __shfl_xor_sync(0xffffffffu, v, 1);
        v += __shfl_xor_sync(0xffffffffu, v, 2);
        inv[h] = 1.0f / v;
    }
    const int b = bh >> 4, hh = bh & 15;
    const size_t r1 = ((size_t)(b * NN + row0 + wq + g)) * DD + hh * HD + 2 * tg;
    const size_t r2 = r1 + (size_t)8 * DD;
#pragma unroll
    for (int jo = 0; jo < 8; jo++) {
        uint32_t hi, lo;
        packsplit_h(O[jo][0] * inv[0], O[jo][1] * inv[0], hi, lo);
        *(uint32_t*)(g_oh + r1 + 8 * jo) = hi;
        *(uint32_t*)(g_ol + r1 + 8 * jo) = lo;
        packsplit_h(O[jo][2] * inv[1], O[jo][3] * inv[1], hi, lo);
        *(uint32_t*)(g_oh + r2 + 8 * jo) = hi;
        *(uint32_t*)(g_ol + r2 + 8 * jo) = lo;
    }
}

// ---------------- launch ----------------
extern "C" void kernel_launch(void* const* d_in, const int* in_sizes, int n_in,
                              void* d_out, int out_size)
{
    const float* x    = (const float*)d_in[0];
    const float* bias = (const float*)d_in[1];
    const float* W[4] = {(const float*)d_in[2], (const float*)d_in[3],
                         (const float*)d_in[4], (const float*)d_in[5]};
    float* out = (float*)d_out;

    __half *xh, *xl, *wq, *qh, *ql, *kk, *vv, *oh, *ol;
    cudaGetSymbolAddress((void**)&xh, g_xh);
    cudaGetSymbolAddress((void**)&xl, g_xl);
    cudaGetSymbolAddress((void**)&wq, g_w);
    cudaGetSymbolAddress((void**)&qh, g_qh);
    cudaGetSymbolAddress((void**)&ql, g_ql);
    cudaGetSymbolAddress((void**)&kk, g_k);
    cudaGetSymbolAddress((void**)&vv, g_v);
    cudaGetSymbolAddress((void**)&oh, g_oh);
    cudaGetSymbolAddress((void**)&ol, g_ol);

    cudaFuncSetAttribute(gemm_mma<0>, cudaFuncAttributeMaxDynamicSharedMemorySize, GSMEM_BYTES);
    cudaFuncSetAttribute(gemm_mma<1>, cudaFuncAttributeMaxDynamicSharedMemorySize, GSMEM_BYTES);
    cudaFuncSetAttribute(gemm_mma<2>, cudaFuncAttributeMaxDynamicSharedMemorySize, GSMEM_BYTES);
    cudaFuncSetAttribute(attn_mma, cudaFuncAttributeMaxDynamicSharedMemorySize, ASMEM);

    const int NX = BB*NN*DD;
    const int NW = DD*DD;

    split_x_kernel<<<NX/512, 256>>>(x, xh, xl, NX/2);
    for (int i = 0; i < 4; i++)
        round_w_kernel<<<NW/512, 256>>>(W[i], wq + (size_t)i*NW, NW/2);

    dim3 gg(DD/128, (BB*NN)/128);   // (8, 32)
    gemm_mma<1><<<gg, 256, GSMEM_BYTES>>>(xh, xl, wq + 0*(size_t)NW, nullptr, qh, ql, 0.125f);
    gemm_mma<2><<<gg, 256, GSMEM_BYTES>>>(xh, xl, wq + 1*(size_t)NW, nullptr, kk, nullptr, 1.0f);
    gemm_mma<2><<<gg, 256, GSMEM_BYTES>>>(xh, xl, wq + 2*(size_t)NW, nullptr, vv, nullptr, 1.0f);

    attn_mma<<<dim3(BH, NN/128), 256, ASMEM>>>(bias);

    gemm_mma<0><<<gg, 256, GSMEM_BYTES>>>(oh, ol, wq + 3*(size_t)NW, out, nullptr, nullptr, 1.0f);
}

// round 10
// speedup vs baseline: 4.4462x; 1.0033x over previous
#include <cuda_runtime.h>
#include <cuda_fp16.h>
#include <math.h>
#include <stdint.h>

#define BB 4
#define NN 1024
#define DD 1024
#define HH 16
#define HD 64
#define BH (BB*HH)

// ---------------- scratch (device globals; allocation-free) ----------------
__device__ __half g_xh[BB*NN*DD];      // x hi
__device__ __half g_xl[BB*NN*DD];      // x lo
__device__ __half g_w[4][DD*DD];       // Wq,Wk,Wv,Wo fp16

__device__ __half g_qh[BH*NN*HD];      // Q hi (pre-scaled by 0.125)
__device__ __half g_ql[BH*NN*HD];      // Q lo
__device__ __half g_k [BH*NN*HD];      // K single
__device__ __half g_v [BH*NN*HD];      // V single

__device__ __half g_oh[BB*NN*DD];      // attention out hi [B,N,D]
__device__ __half g_ol[BB*NN*DD];      // attention out lo

// ---------------- helpers ----------------
__device__ __forceinline__ uint32_t smem_u32(const void* p) {
    uint32_t a;
    asm("{ .reg .u64 t; cvta.to.shared.u64 t, %1; cvt.u32.u64 %0, t; }" : "=r"(a) : "l"(p));
    return a;
}
__device__ __forceinline__ void mma16816(float* d, const uint32_t* a, const uint32_t* b) {
    asm volatile(
        "mma.sync.aligned.m16n8k16.row.col.f32.f16.f16.f32 "
        "{%0,%1,%2,%3}, {%4,%5,%6,%7}, {%8,%9}, {%0,%1,%2,%3};"
        : "+f"(d[0]), "+f"(d[1]), "+f"(d[2]), "+f"(d[3])
        : "r"(a[0]), "r"(a[1]), "r"(a[2]), "r"(a[3]), "r"(b[0]), "r"(b[1]));
}
__device__ __forceinline__ void ldsm_x4(uint32_t* r, uint32_t addr) {
    asm volatile("ldmatrix.sync.aligned.m8n8.x4.shared.b16 {%0,%1,%2,%3}, [%4];"
        : "=r"(r[0]), "=r"(r[1]), "=r"(r[2]), "=r"(r[3]) : "r"(addr));
}
__device__ __forceinline__ void ldsm_x4_t(uint32_t* r, uint32_t addr) {
    asm volatile("ldmatrix.sync.aligned.m8n8.x4.trans.shared.b16 {%0,%1,%2,%3}, [%4];"
        : "=r"(r[0]), "=r"(r[1]), "=r"(r[2]), "=r"(r[3]) : "r"(addr));
}
#define CP_ASYNC16(sdst, gsrc) \
    asm volatile("cp.async.cg.shared.global [%0], [%1], 16;" :: "r"(sdst), "l"(gsrc))
#define CP_COMMIT() asm volatile("cp.async.commit_group;" ::: "memory")
#define CP_WAIT0()  asm volatile("cp.async.wait_group 0;" ::: "memory")
#define CP_WAIT1()  asm volatile("cp.async.wait_group 1;" ::: "memory")

__device__ __forceinline__ void packsplit_h(float f0, float f1, uint32_t& hi, uint32_t& lo) {
    __half2 h = __floats2half2_rn(f0, f1);
    float r0 = f0 - __low2float(h);
    float r1 = f1 - __high2float(h);
    __half2 l = __floats2half2_rn(r0, r1);
    hi = *reinterpret_cast<uint32_t*>(&h);
    lo = *reinterpret_cast<uint32_t*>(&l);
}
__device__ __forceinline__ uint32_t pack_h(float f0, float f1) {
    __half2 h = __floats2half2_rn(f0, f1);
    return *reinterpret_cast<uint32_t*>(&h);
}

// ---------------- prep kernels ----------------
__global__ __launch_bounds__(256) void split_x_kernel(const float* __restrict__ s,
                                                      __half* __restrict__ h,
                                                      __half* __restrict__ l, int n2)
{
    int i = blockIdx.x * 256 + threadIdx.x;
    if (i < n2) {
        float2 v = ((const float2*)s)[i];
        uint32_t hi, lo;
        packsplit_h(v.x, v.y, hi, lo);
        ((uint32_t*)h)[i] = hi;
        ((uint32_t*)l)[i] = lo;
    }
}
// all 4 weights in one launch: blockIdx.y selects source, dst is contiguous g_w
__global__ __launch_bounds__(256) void round_w4_kernel(
    const float* __restrict__ w0, const float* __restrict__ w1,
    const float* __restrict__ w2, const float* __restrict__ w3,
    __half* __restrict__ h, int n2)
{
    const float* src[4] = {w0, w1, w2, w3};
    int i = blockIdx.x * 256 + threadIdx.x;
    if (i < n2) {
        float2 v = ((const float2*)src[blockIdx.y])[i];
        ((uint32_t*)h)[(size_t)blockIdx.y * n2 + i] = pack_h(v.x, v.y);
    }
}

// ---------------- 2-term fp16 GEMM (HMMA + ldmatrix, 3-stage cp.async) ----------------
#define KS 32
#define SS 40
#define RB (SS*2)                      // 80 bytes/row
#define TILE_BYTES (128*RB)            // 10240
#define STAGE_BYTES (3*TILE_BYTES)     // 30720: Ah, Al, B
#define GSMEM_BYTES (3*STAGE_BYTES)    // 92160, 3 stages
#define NSTG (DD/KS)                   // 32

// MODE0: fp32 out[m*1024+n] (out-projection)
// MODE1: fused QKV — blockIdx.z: 0=Q (split hi/lo, *0.125), 1=K single, 2=V single
template<int MODE>
__global__ __launch_bounds__(256) void gemm_mma(
    const __half* __restrict__ Ah, const __half* __restrict__ Al,
    const __half* __restrict__ Bw,
    float* __restrict__ outF, __half* __restrict__ o1,
    __half* __restrict__ o2, __half* __restrict__ o3)
{
    extern __shared__ __align__(16) char smem[];
    const int tid = threadIdx.x;
    const int wid = tid >> 5, lane = tid & 31;
    const int g = lane >> 2, tg = lane & 3;
    const int m0 = blockIdx.y * 128, n0 = blockIdx.x * 128;
    const int wm = (wid & 1) * 64, wn = (wid >> 1) * 32;
    const int z = (MODE == 1) ? blockIdx.z : 0;

    const uint32_t sbase = smem_u32(smem);
    const __half* Bz = (MODE == 1) ? (Bw + (size_t)z * DD * DD) : Bw;
    const __half* srcs[3] = {Ah, Al, Bz};

    auto prefetch = [&](int s) {
        const int k0 = s * KS;
        const uint32_t dst0 = sbase + (uint32_t)(s % 3) * STAGE_BYTES;
#pragma unroll
        for (int t = 0; t < 3; t++) {
            const __half* sp = srcs[t];
            const int rb = (t < 2) ? m0 : n0;
#pragma unroll
            for (int i = 0; i < 2; i++) {
                int idx = tid + i * 256;
                int row = idx >> 2, c = idx & 3;
                const void* gsrc = sp + (size_t)(rb + row) * DD + k0 + c * 8;
                CP_ASYNC16(dst0 + t * TILE_BYTES + row * RB + c * 16, gsrc);
            }
        }
        CP_COMMIT();
    };

    float acc[4][4][4];
#pragma unroll
    for (int i = 0; i < 4; i++)
#pragma unroll
        for (int j = 0; j < 4; j++)
#pragma unroll
            for (int c = 0; c < 4; c++) acc[i][j][c] = 0.f;

    const uint32_t laneA = (lane & 15) * RB + (lane >> 4) * 16;
    const uint32_t laneB = ((lane & 7) + (lane >> 4) * 8) * RB + ((lane >> 3) & 1) * 16;

    prefetch(0);
    prefetch(1);
    for (int s = 0; s < NSTG; s++) {
        if (s == NSTG - 1) { CP_WAIT0(); } else { CP_WAIT1(); }
        __syncthreads();
        if (s + 2 < NSTG) prefetch(s + 2);
        const uint32_t st = sbase + (uint32_t)(s % 3) * STAGE_BYTES;

#pragma unroll
        for (int ks = 0; ks < 2; ks++) {
            const int kb2 = ks * 32;
            uint32_t ah[4][4], al[4][4], bh[8];
#pragma unroll
            for (int i = 0; i < 4; i++) {
                uint32_t aA = st + (wm + 16 * i) * RB + kb2 + laneA;
                ldsm_x4(ah[i], aA);
                ldsm_x4(al[i], aA + TILE_BYTES);
            }
            {
                uint32_t b0 = st + 2 * TILE_BYTES + wn * RB + kb2 + laneB;
                ldsm_x4(bh,     b0);
                ldsm_x4(bh + 4, b0 + 16 * RB);
            }
#pragma unroll
            for (int i = 0; i < 4; i++)
#pragma unroll
                for (int j = 0; j < 4; j++) {
                    mma16816(acc[i][j], ah[i], bh + 2 * j);
                    mma16816(acc[i][j], al[i], bh + 2 * j);
                }
        }
    }

#pragma unroll
    for (int i = 0; i < 4; i++) {
        int mA = m0 + wm + i * 16 + g;
#pragma unroll
        for (int j = 0; j < 4; j++) {
            int c = n0 + wn + j * 8 + 2 * tg;
            if (MODE == 0) {
                *(float2*)(outF + (size_t)mA * DD + c) =
                    make_float2(acc[i][j][0], acc[i][j][1]);
                *(float2*)(outF + (size_t)(mA + 8) * DD + c) =
                    make_float2(acc[i][j][2], acc[i][j][3]);
            } else {
                int h = c >> 6, t = c & 63;
                int b1 = mA >> 10, n1 = mA & 1023;
                int b2 = (mA + 8) >> 10, n2 = (mA + 8) & 1023;
                size_t i1 = ((size_t)(b1 * HH + h) * NN + n1) * HD + t;
                size_t i2 = ((size_t)(b2 * HH + h) * NN + n2) * HD + t;
                if (z == 0) {   // Q: split hi/lo, scale 0.125
                    uint32_t hi, lo;
                    packsplit_h(acc[i][j][0] * 0.125f, acc[i][j][1] * 0.125f, hi, lo);
                    *(uint32_t*)(o1 + i1) = hi;
                    *(uint32_t*)(o2 + i1) = lo;
                    packsplit_h(acc[i][j][2] * 0.125f, acc[i][j][3] * 0.125f, hi, lo);
                    *(uint32_t*)(o1 + i2) = hi;
                    *(uint32_t*)(o2 + i2) = lo;
                } else {        // K or V: single fp16
                    __half* dst = (z == 1) ? o3 : (o3 + (size_t)BH * NN * HD);
                    *(uint32_t*)(dst + i1) = pack_h(acc[i][j][0], acc[i][j][1]);
                    *(uint32_t*)(dst + i2) = pack_h(acc[i][j][2], acc[i][j][3]);
                }
            }
        }
    }
}

// ---------------- flash attention (fp16 2-term, fixed-offset softmax) ----------------
#define ATS 72
#define ATSB (ATS*2)                   // 144 bytes/row
#define ATILE (128*ATSB)               // 18432
#define AKV_STAGE (2*ATILE)            // 36864: K, V
#define ASMEM (2*ATILE + 2*AKV_STAGE)  // 110592
#define SOFF 8.0f                      // fixed softmax offset (shift-exact)

__global__ __launch_bounds__(256) void attn_mma(const float* __restrict__ bias)
{
    extern __shared__ __align__(16) char smem[];
    const int tid = threadIdx.x, wid = tid >> 5, lane = tid & 31;
    const int g = lane >> 2, tg = lane & 3;
    const int bh = blockIdx.x;
    const int row0 = blockIdx.y * 128;
    const int wq = wid * 16;
    const uint32_t sb = smem_u32(smem);

    const __half* qhp = g_qh + (size_t)bh * NN * HD;
    const __half* qlp = g_ql + (size_t)bh * NN * HD;
    const __half* kp  = g_k  + (size_t)bh * NN * HD;
    const __half* vp  = g_v  + (size_t)bh * NN * HD;

    auto issue_kv = [&](int c) {
        const uint32_t stg = sb + 2 * ATILE + (uint32_t)(c & 1) * AKV_STAGE;
#pragma unroll
        for (int i = 0; i < 4; i++) {
            int idx = tid + i * 256;
            int row = idx >> 3, ch = idx & 7;
            size_t go = (size_t)(c * 128 + row) * HD + ch * 8;
            uint32_t dst = stg + row * ATSB + ch * 16;
            CP_ASYNC16(dst,         kp + go);
            CP_ASYNC16(dst + ATILE, vp + go);
        }
    };

#pragma unroll
    for (int i = 0; i < 4; i++) {
        int idx = tid + i * 256;
        int row = idx >> 3, ch = idx & 7;
        size_t go = (size_t)(row0 + row) * HD + ch * 8;
        uint32_t dst = sb + row * ATSB + ch * 16;
        CP_ASYNC16(dst,         qhp + go);
        CP_ASYNC16(dst + ATILE, qlp + go);
    }
    issue_kv(0);
    CP_COMMIT();

    float sA[16][4];
    float O[8][4];
#pragma unroll
    for (int j = 0; j < 8; j++)
#pragma unroll
        for (int c = 0; c < 4; c++) O[j][c] = 0.f;
    float ls[2] = {0.f, 0.f};
    uint32_t qfh[4][4], qfl[4][4];

    const float* biasP = bias + ((size_t)bh * NN + row0 + wq + g) * NN + 2 * tg;

    const uint32_t laneQ = (lane & 15) * ATSB + (lane >> 4) * 16;
    const uint32_t laneK = (lane & 7) * ATSB + (lane >> 3) * 16;
    const uint32_t laneV = ((lane & 7) + ((lane >> 3) & 1) * 8) * ATSB + (lane >> 4) * 16;

    for (int c = 0; c < 8; c++) {
        CP_WAIT0();
        __syncthreads();
        if (c == 0) {
#pragma unroll
            for (int t = 0; t < 4; t++) {
                uint32_t qa = sb + wq * ATSB + t * 32 + laneQ;
                ldsm_x4(qfh[t], qa);
                ldsm_x4(qfl[t], qa + ATILE);
            }
        }
        if (c + 1 < 8) { issue_kv(c + 1); CP_COMMIT(); }

        const uint32_t kh_b = sb + 2 * ATILE + (uint32_t)(c & 1) * AKV_STAGE;

        // ---- S = bias + Q K^T ----
        const float* bp = biasP + c * 128;
#pragma unroll
        for (int j = 0; j < 16; j++) {
            float2 u = *(const float2*)(bp + 8 * j);
            float2 w = *(const float2*)(bp + 8 * NN + 8 * j);
            sA[j][0] = u.x; sA[j][1] = u.y; sA[j][2] = w.x; sA[j][3] = w.y;
        }
#pragma unroll 4
        for (int j = 0; j < 16; j++) {
            uint32_t kf[8];
            uint32_t ka = kh_b + j * 8 * ATSB + laneK;
            ldsm_x4(kf,     ka);
            ldsm_x4(kf + 4, ka + 64);
#pragma unroll
            for (int t = 0; t < 4; t++) {
                mma16816(sA[j], qfh[t], kf + 2 * t);
                mma16816(sA[j], qfl[t], kf + 2 * t);
            }
        }

        // ---- P = exp(S - SOFF); accumulate row sums (no running max) ----
        {
            float p0 = 0.f, p1 = 0.f;
#pragma unroll
            for (int j = 0; j < 16; j++) {
                float e0 = __expf(sA[j][0] - SOFF);
                float e1 = __expf(sA[j][1] - SOFF);
                float e2 = __expf(sA[j][2] - SOFF);
                float e3 = __expf(sA[j][3] - SOFF);
                sA[j][0] = e0; sA[j][1] = e1; sA[j][2] = e2; sA[j][3] = e3;
                p0 += e0 + e1;
                p1 += e2 + e3;
            }
            ls[0] += p0;
            ls[1] += p1;
        }

        // ---- O += P V  (P split hi/lo, V single) ----
        const uint32_t vh_b = kh_b + ATILE;
#pragma unroll 2
        for (int t = 0; t < 8; t++) {
            uint32_t aph[4], apl[4];
            packsplit_h(sA[2 * t][0],     sA[2 * t][1],     aph[0], apl[0]);
            packsplit_h(sA[2 * t][2],     sA[2 * t][3],     aph[1], apl[1]);
            packsplit_h(sA[2 * t + 1][0], sA[2 * t + 1][1], aph[2], apl[2]);
            packsplit_h(sA[2 * t + 1][2], sA[2 * t + 1][3], aph[3], apl[3]);
#pragma unroll
            for (int jp = 0; jp < 8; jp += 2) {
                uint32_t vf[4];
                uint32_t va = vh_b + t * 16 * ATSB + jp * 16 + laneV;
                ldsm_x4_t(vf, va);
                mma16816(O[jp],     aph, vf);
                mma16816(O[jp],     apl, vf);
                mma16816(O[jp + 1], aph, vf + 2);
                mma16816(O[jp + 1], apl, vf + 2);
            }
        }
    }

    // ---- finalize ----
    float inv[2];
#pragma unroll
    for (int h = 0; h < 2; h++) {
        float v = ls[h];
        v += __shfl_xor_sync(0xffffffffu, v, 1);
        v += __shfl_xor_sync(0xffffffffu, v, 2);
        inv[h] = 1.0f / v;
    }
    const int b = bh >> 4, hh = bh & 15;
    const size_t r1 = ((size_t)(b * NN + row0 + wq + g)) * DD + hh * HD + 2 * tg;
    const size_t r2 = r1 + (size_t)8 * DD;
#pragma unroll
    for (int jo = 0; jo < 8; jo++) {
        uint32_t hi, lo;
        packsplit_h(O[jo][0] * inv[0], O[jo][1] * inv[0], hi, lo);
        *(uint32_t*)(g_oh + r1 + 8 * jo) = hi;
        *(uint32_t*)(g_ol + r1 + 8 * jo) = lo;
        packsplit_h(O[jo][2] * inv[1], O[jo][3] * inv[1], hi, lo);
        *(uint32_t*)(g_oh + r2 + 8 * jo) = hi;
        *(uint32_t*)(g_ol + r2 + 8 * jo) = lo;
    }
}

// ---------------- launch ----------------
extern "C" void kernel_launch(void* const* d_in, const int* in_sizes, int n_in,
                              void* d_out, int out_size)
{
    const float* x    = (const float*)d_in[0];
    const float* bias = (const float*)d_in[1];
    float* out = (float*)d_out;

    __half *xh, *xl, *wq, *qh, *ql, *kk, *oh, *ol;
    cudaGetSymbolAddress((void**)&xh, g_xh);
    cudaGetSymbolAddress((void**)&xl, g_xl);
    cudaGetSymbolAddress((void**)&wq, g_w);
    cudaGetSymbolAddress((void**)&qh, g_qh);
    cudaGetSymbolAddress((void**)&ql, g_ql);
    cudaGetSymbolAddress((void**)&kk, g_k);   // g_v follows layout via offset
    cudaGetSymbolAddress((void**)&oh, g_oh);
    cudaGetSymbolAddress((void**)&ol, g_ol);

    cudaFuncSetAttribute(gemm_mma<0>, cudaFuncAttributeMaxDynamicSharedMemorySize, GSMEM_BYTES);
    cudaFuncSetAttribute(gemm_mma<1>, cudaFuncAttributeMaxDynamicSharedMemorySize, GSMEM_BYTES);
    cudaFuncSetAttribute(attn_mma, cudaFuncAttributeMaxDynamicSharedMemorySize, ASMEM);

    const int NX = BB*NN*DD;
    const int NW = DD*DD;

    split_x_kernel<<<NX/512, 256>>>(x, xh, xl, NX/2);
    round_w4_kernel<<<dim3(NW/512, 4), 256>>>((const float*)d_in[2], (const float*)d_in[3],
                                              (const float*)d_in[4], (const float*)d_in[5],
                                              wq, NW/2);

    // fused QKV: z=0 Q(split,scaled), z=1 K, z=2 V  (K and V via o3 base = g_k; V offset inside)
    dim3 gqkv(DD/128, (BB*NN)/128, 3);
    gemm_mma<1><<<gqkv, 256, GSMEM_BYTES>>>(xh, xl, wq, nullptr, qh, ql, kk);

    attn_mma<<<dim3(BH, NN/128), 256, ASMEM>>>(bias);

    gemm_mma<0><<<dim3(DD/128, (BB*NN)/128), 256, GSMEM_BYTES>>>(
        oh, ol, wq + 3*(size_t)NW, out, nullptr, nullptr, nullptr);
}

// round 11
// speedup vs baseline: 5.0120x; 1.1273x over previous
#include <cuda_runtime.h>
#include <cuda_fp16.h>
#include <math.h>
#include <stdint.h>

#define BB 4
#define NN 1024
#define DD 1024
#define HH 16
#define HD 64
#define BH (BB*HH)

// ---------------- scratch (device globals; allocation-free) ----------------
__device__ __half g_xh[BB*NN*DD];      // x hi
__device__ __half g_xl[BB*NN*DD];      // x lo
__device__ __half g_w[4][DD*DD];       // Wq,Wk,Wv,Wo fp16

__device__ __half g_qh[BH*NN*HD];      // Q hi (pre-scaled by 0.125)
__device__ __half g_ql[BH*NN*HD];      // Q lo
__device__ __half g_k [BH*NN*HD];      // K single
__device__ __half g_v [BH*NN*HD];      // V single

__device__ __half g_oh[BB*NN*DD];      // attention out hi [B,N,D]
__device__ __half g_ol[BB*NN*DD];      // attention out lo

// ---------------- helpers ----------------
__device__ __forceinline__ uint32_t smem_u32(const void* p) {
    uint32_t a;
    asm("{ .reg .u64 t; cvta.to.shared.u64 t, %1; cvt.u32.u64 %0, t; }" : "=r"(a) : "l"(p));
    return a;
}
__device__ __forceinline__ void mma16816(float* d, const uint32_t* a, const uint32_t* b) {
    asm volatile(
        "mma.sync.aligned.m16n8k16.row.col.f32.f16.f16.f32 "
        "{%0,%1,%2,%3}, {%4,%5,%6,%7}, {%8,%9}, {%0,%1,%2,%3};"
        : "+f"(d[0]), "+f"(d[1]), "+f"(d[2]), "+f"(d[3])
        : "r"(a[0]), "r"(a[1]), "r"(a[2]), "r"(a[3]), "r"(b[0]), "r"(b[1]));
}
__device__ __forceinline__ void ldsm_x4(uint32_t* r, uint32_t addr) {
    asm volatile("ldmatrix.sync.aligned.m8n8.x4.shared.b16 {%0,%1,%2,%3}, [%4];"
        : "=r"(r[0]), "=r"(r[1]), "=r"(r[2]), "=r"(r[3]) : "r"(addr));
}
__device__ __forceinline__ void ldsm_x4_t(uint32_t* r, uint32_t addr) {
    asm volatile("ldmatrix.sync.aligned.m8n8.x4.trans.shared.b16 {%0,%1,%2,%3}, [%4];"
        : "=r"(r[0]), "=r"(r[1]), "=r"(r[2]), "=r"(r[3]) : "r"(addr));
}
#define CP_ASYNC16(sdst, gsrc) \
    asm volatile("cp.async.cg.shared.global [%0], [%1], 16;" :: "r"(sdst), "l"(gsrc))
#define CP_COMMIT() asm volatile("cp.async.commit_group;" ::: "memory")
#define CP_WAIT0()  asm volatile("cp.async.wait_group 0;" ::: "memory")
#define CP_WAIT1()  asm volatile("cp.async.wait_group 1;" ::: "memory")

#define SWZ(o) ((o) ^ (((o) >> 3) & 0x70))    // SW128 for 128-byte rows

__device__ __forceinline__ void packsplit_h(float f0, float f1, uint32_t& hi, uint32_t& lo) {
    __half2 h = __floats2half2_rn(f0, f1);
    float r0 = f0 - __low2float(h);
    float r1 = f1 - __high2float(h);
    __half2 l = __floats2half2_rn(r0, r1);
    hi = *reinterpret_cast<uint32_t*>(&h);
    lo = *reinterpret_cast<uint32_t*>(&l);
}
__device__ __forceinline__ uint32_t pack_h(float f0, float f1) {
    __half2 h = __floats2half2_rn(f0, f1);
    return *reinterpret_cast<uint32_t*>(&h);
}

// ---------------- prep kernels ----------------
__global__ __launch_bounds__(256) void split_x_kernel(const float* __restrict__ s,
                                                      __half* __restrict__ h,
                                                      __half* __restrict__ l, int n2)
{
    int i = blockIdx.x * 256 + threadIdx.x;
    if (i < n2) {
        float2 v = ((const float2*)s)[i];
        uint32_t hi, lo;
        packsplit_h(v.x, v.y, hi, lo);
        ((uint32_t*)h)[i] = hi;
        ((uint32_t*)l)[i] = lo;
    }
}
__global__ __launch_bounds__(256) void round_w4_kernel(
    const float* __restrict__ w0, const float* __restrict__ w1,
    const float* __restrict__ w2, const float* __restrict__ w3,
    __half* __restrict__ h, int n2)
{
    const float* src[4] = {w0, w1, w2, w3};
    int i = blockIdx.x * 256 + threadIdx.x;
    if (i < n2) {
        float2 v = ((const float2*)src[blockIdx.y])[i];
        ((uint32_t*)h)[(size_t)blockIdx.y * n2 + i] = pack_h(v.x, v.y);
    }
}

// ---------------- 2-term fp16 GEMM (HMMA + ldmatrix, 3-stage cp.async) ----------------
#define KS 32
#define SS 40
#define RB (SS*2)
#define TILE_BYTES (128*RB)
#define STAGE_BYTES (3*TILE_BYTES)
#define GSMEM_BYTES (3*STAGE_BYTES)
#define NSTG (DD/KS)

template<int MODE>
__global__ __launch_bounds__(256) void gemm_mma(
    const __half* __restrict__ Ah, const __half* __restrict__ Al,
    const __half* __restrict__ Bw,
    float* __restrict__ outF, __half* __restrict__ o1,
    __half* __restrict__ o2, __half* __restrict__ o3)
{
    extern __shared__ __align__(16) char smem[];
    const int tid = threadIdx.x;
    const int wid = tid >> 5, lane = tid & 31;
    const int g = lane >> 2, tg = lane & 3;
    const int m0 = blockIdx.y * 128, n0 = blockIdx.x * 128;
    const int wm = (wid & 1) * 64, wn = (wid >> 1) * 32;
    const int z = (MODE == 1) ? blockIdx.z : 0;

    const uint32_t sbase = smem_u32(smem);
    const __half* Bz = (MODE == 1) ? (Bw + (size_t)z * DD * DD) : Bw;
    const __half* srcs[3] = {Ah, Al, Bz};

    auto prefetch = [&](int s) {
        const int k0 = s * KS;
        const uint32_t dst0 = sbase + (uint32_t)(s % 3) * STAGE_BYTES;
#pragma unroll
        for (int t = 0; t < 3; t++) {
            const __half* sp = srcs[t];
            const int rb = (t < 2) ? m0 : n0;
#pragma unroll
            for (int i = 0; i < 2; i++) {
                int idx = tid + i * 256;
                int row = idx >> 2, c = idx & 3;
                const void* gsrc = sp + (size_t)(rb + row) * DD + k0 + c * 8;
                CP_ASYNC16(dst0 + t * TILE_BYTES + row * RB + c * 16, gsrc);
            }
        }
        CP_COMMIT();
    };

    float acc[4][4][4];
#pragma unroll
    for (int i = 0; i < 4; i++)
#pragma unroll
        for (int j = 0; j < 4; j++)
#pragma unroll
            for (int c = 0; c < 4; c++) acc[i][j][c] = 0.f;

    const uint32_t laneA = (lane & 15) * RB + (lane >> 4) * 16;
    const uint32_t laneB = ((lane & 7) + (lane >> 4) * 8) * RB + ((lane >> 3) & 1) * 16;

    prefetch(0);
    prefetch(1);
    for (int s = 0; s < NSTG; s++) {
        if (s == NSTG - 1) { CP_WAIT0(); } else { CP_WAIT1(); }
        __syncthreads();
        if (s + 2 < NSTG) prefetch(s + 2);
        const uint32_t st = sbase + (uint32_t)(s % 3) * STAGE_BYTES;

#pragma unroll
        for (int ks = 0; ks < 2; ks++) {
            const int kb2 = ks * 32;
            uint32_t ah[4][4], al[4][4], bh[8];
#pragma unroll
            for (int i = 0; i < 4; i++) {
                uint32_t aA = st + (wm + 16 * i) * RB + kb2 + laneA;
                ldsm_x4(ah[i], aA);
                ldsm_x4(al[i], aA + TILE_BYTES);
            }
            {
                uint32_t b0 = st + 2 * TILE_BYTES + wn * RB + kb2 + laneB;
                ldsm_x4(bh,     b0);
                ldsm_x4(bh + 4, b0 + 16 * RB);
            }
#pragma unroll
            for (int i = 0; i < 4; i++)
#pragma unroll
                for (int j = 0; j < 4; j++) {
                    mma16816(acc[i][j], ah[i], bh + 2 * j);
                    mma16816(acc[i][j], al[i], bh + 2 * j);
                }
        }
    }

#pragma unroll
    for (int i = 0; i < 4; i++) {
        int mA = m0 + wm + i * 16 + g;
#pragma unroll
        for (int j = 0; j < 4; j++) {
            int c = n0 + wn + j * 8 + 2 * tg;
            if (MODE == 0) {
                *(float2*)(outF + (size_t)mA * DD + c) =
                    make_float2(acc[i][j][0], acc[i][j][1]);
                *(float2*)(outF + (size_t)(mA + 8) * DD + c) =
                    make_float2(acc[i][j][2], acc[i][j][3]);
            } else {
                int h = c >> 6, t = c & 63;
                int b1 = mA >> 10, n1 = mA & 1023;
                int b2 = (mA + 8) >> 10, n2 = (mA + 8) & 1023;
                size_t i1 = ((size_t)(b1 * HH + h) * NN + n1) * HD + t;
                size_t i2 = ((size_t)(b2 * HH + h) * NN + n2) * HD + t;
                if (z == 0) {
                    uint32_t hi, lo;
                    packsplit_h(acc[i][j][0] * 0.125f, acc[i][j][1] * 0.125f, hi, lo);
                    *(uint32_t*)(o1 + i1) = hi;
                    *(uint32_t*)(o2 + i1) = lo;
                    packsplit_h(acc[i][j][2] * 0.125f, acc[i][j][3] * 0.125f, hi, lo);
                    *(uint32_t*)(o1 + i2) = hi;
                    *(uint32_t*)(o2 + i2) = lo;
                } else {
                    __half* dst = (z == 1) ? o3 : (o3 + (size_t)BH * NN * HD);
                    *(uint32_t*)(dst + i1) = pack_h(acc[i][j][0], acc[i][j][1]);
                    *(uint32_t*)(dst + i2) = pack_h(acc[i][j][2], acc[i][j][3]);
                }
            }
        }
    }
}

// ---------------- flash attention (fp16 2-term, swizzled smem, 2 CTA/SM) ----------------
#define ATILE 16384                    // 128 rows x 128 B (swizzled)
#define AKV_STAGE (2*ATILE)            // 32768: K, V
#define ASMEM (2*ATILE + 2*AKV_STAGE)  // 98304
#define SOFF 8.0f

__global__ __launch_bounds__(256, 2) void attn_mma(const float* __restrict__ bias)
{
    extern __shared__ __align__(1024) char smem[];
    const int tid = threadIdx.x, wid = tid >> 5, lane = tid & 31;
    const int g = lane >> 2, tg = lane & 3;
    const int bh = blockIdx.x;
    const int row0 = blockIdx.y * 128;
    const int wq = wid * 16;
    const uint32_t sb = smem_u32(smem);

    const __half* qhp = g_qh + (size_t)bh * NN * HD;
    const __half* qlp = g_ql + (size_t)bh * NN * HD;
    const __half* kp  = g_k  + (size_t)bh * NN * HD;
    const __half* vp  = g_v  + (size_t)bh * NN * HD;

    auto issue_kv = [&](int c) {
        const uint32_t stg = sb + 2 * ATILE + (uint32_t)(c & 1) * AKV_STAGE;
#pragma unroll
        for (int i = 0; i < 4; i++) {
            int idx = tid + i * 256;
            int row = idx >> 3, ch = idx & 7;
            size_t go = (size_t)(c * 128 + row) * HD + ch * 8;
            uint32_t so = SWZ((uint32_t)(row * 128 + ch * 16));
            CP_ASYNC16(stg + so,         kp + go);
            CP_ASYNC16(stg + ATILE + so, vp + go);
        }
    };

#pragma unroll
    for (int i = 0; i < 4; i++) {
        int idx = tid + i * 256;
        int row = idx >> 3, ch = idx & 7;
        size_t go = (size_t)(row0 + row) * HD + ch * 8;
        uint32_t so = SWZ((uint32_t)(row * 128 + ch * 16));
        CP_ASYNC16(sb + so,         qhp + go);
        CP_ASYNC16(sb + ATILE + so, qlp + go);
    }
    issue_kv(0);
    CP_COMMIT();

    float sA[16][4];
    float O[8][4];
#pragma unroll
    for (int j = 0; j < 8; j++)
#pragma unroll
        for (int c = 0; c < 4; c++) O[j][c] = 0.f;
    float ls[2] = {0.f, 0.f};
    uint32_t qfh[4][4], qfl[4][4];

    const float* biasP = bias + ((size_t)bh * NN + row0 + wq + g) * NN + 2 * tg;

    for (int c = 0; c < 8; c++) {
        // ---- bias LDGs first: fly during the cp.async wait ----
        const float* bp = biasP + c * 128;
#pragma unroll
        for (int j = 0; j < 16; j++) {
            float2 u = *(const float2*)(bp + 8 * j);
            float2 w = *(const float2*)(bp + 8 * NN + 8 * j);
            sA[j][0] = u.x; sA[j][1] = u.y; sA[j][2] = w.x; sA[j][3] = w.y;
        }

        CP_WAIT0();
        __syncthreads();
        if (c == 0) {
#pragma unroll
            for (int t = 0; t < 4; t++) {
#pragma unroll
                for (int r2 = 0; r2 < 1; r2++) {}  // (kept simple)
                uint32_t qoff = (uint32_t)((wq + (lane & 15)) * 128 + t * 32 + (lane >> 4) * 16);
                uint32_t qa = sb + SWZ(qoff);
                ldsm_x4(qfh[t], qa);
                ldsm_x4(qfl[t], qa + ATILE);   // ATILE is 1KB-aligned; SWZ bits < 1KB
            }
        }
        if (c + 1 < 8) { issue_kv(c + 1); CP_COMMIT(); }

        const uint32_t kh_b = sb + 2 * ATILE + (uint32_t)(c & 1) * AKV_STAGE;

        // ---- S = bias + Q K^T ----
#pragma unroll 4
        for (int j = 0; j < 16; j++) {
            uint32_t kf[8];
            uint32_t koff = (uint32_t)((j * 8 + (lane & 7)) * 128 + (lane >> 3) * 16);
            ldsm_x4(kf,     kh_b + SWZ(koff));
            ldsm_x4(kf + 4, kh_b + SWZ(koff + 64));
#pragma unroll
            for (int t = 0; t < 4; t++) {
                mma16816(sA[j], qfh[t], kf + 2 * t);
                mma16816(sA[j], qfl[t], kf + 2 * t);
            }
        }

        // ---- P = exp(S - SOFF); accumulate row sums ----
        {
            float p0 = 0.f, p1 = 0.f;
#pragma unroll
            for (int j = 0; j < 16; j++) {
                float e0 = __expf(sA[j][0] - SOFF);
                float e1 = __expf(sA[j][1] - SOFF);
                float e2 = __expf(sA[j][2] - SOFF);
                float e3 = __expf(sA[j][3] - SOFF);
                sA[j][0] = e0; sA[j][1] = e1; sA[j][2] = e2; sA[j][3] = e3;
                p0 += e0 + e1;
                p1 += e2 + e3;
            }
            ls[0] += p0;
            ls[1] += p1;
        }

        // ---- O += P V  (P split hi/lo, V single) ----
        const uint32_t vh_b = kh_b + ATILE;
#pragma unroll 2
        for (int t = 0; t < 8; t++) {
            uint32_t aph[4], apl[4];
            packsplit_h(sA[2 * t][0],     sA[2 * t][1],     aph[0], apl[0]);
            packsplit_h(sA[2 * t][2],     sA[2 * t][3],     aph[1], apl[1]);
            packsplit_h(sA[2 * t + 1][0], sA[2 * t + 1][1], aph[2], apl[2]);
            packsplit_h(sA[2 * t + 1][2], sA[2 * t + 1][3], aph[3], apl[3]);
#pragma unroll
            for (int jp = 0; jp < 8; jp += 2) {
                uint32_t vf[4];
                uint32_t voff = (uint32_t)((t * 16 + (lane & 7) + ((lane >> 3) & 1) * 8) * 128
                                           + jp * 16 + (lane >> 4) * 16);
                ldsm_x4_t(vf, vh_b + SWZ(voff));
                mma16816(O[jp],     aph, vf);
                mma16816(O[jp],     apl, vf);
                mma16816(O[jp + 1], aph, vf + 2);
                mma16816(O[jp + 1], apl, vf + 2);
            }
        }
    }

    // ---- finalize ----
    float inv[2];
#pragma unroll
    for (int h = 0; h < 2; h++) {
        float v = ls[h];
        v += __shfl_xor_sync(0xffffffffu, v, 1);
        v += __shfl_xor_sync(0xffffffffu, v, 2);
        inv[h] = 1.0f / v;
    }
    const int b = bh >> 4, hh = bh & 15;
    const size_t r1 = ((size_t)(b * NN + row0 + wq + g)) * DD + hh * HD + 2 * tg;
    const size_t r2 = r1 + (size_t)8 * DD;
#pragma unroll
    for (int jo = 0; jo < 8; jo++) {
        uint32_t hi, lo;
        packsplit_h(O[jo][0] * inv[0], O[jo][1] * inv[0], hi, lo);
        *(uint32_t*)(g_oh + r1 + 8 * jo) = hi;
        *(uint32_t*)(g_ol + r1 + 8 * jo) = lo;
        packsplit_h(O[jo][2] * inv[1], O[jo][3] * inv[1], hi, lo);
        *(uint32_t*)(g_oh + r2 + 8 * jo) = hi;
        *(uint32_t*)(g_ol + r2 + 8 * jo) = lo;
    }
}

// ---------------- launch ----------------
extern "C" void kernel_launch(void* const* d_in, const int* in_sizes, int n_in,
                              void* d_out, int out_size)
{
    const float* x    = (const float*)d_in[0];
    const float* bias = (const float*)d_in[1];
    float* out = (float*)d_out;

    __half *xh, *xl, *wq, *qh, *ql, *kk, *oh, *ol;
    cudaGetSymbolAddress((void**)&xh, g_xh);
    cudaGetSymbolAddress((void**)&xl, g_xl);
    cudaGetSymbolAddress((void**)&wq, g_w);
    cudaGetSymbolAddress((void**)&qh, g_qh);
    cudaGetSymbolAddress((void**)&ql, g_ql);
    cudaGetSymbolAddress((void**)&kk, g_k);
    cudaGetSymbolAddress((void**)&oh, g_oh);
    cudaGetSymbolAddress((void**)&ol, g_ol);

    cudaFuncSetAttribute(gemm_mma<0>, cudaFuncAttributeMaxDynamicSharedMemorySize, GSMEM_BYTES);
    cudaFuncSetAttribute(gemm_mma<1>, cudaFuncAttributeMaxDynamicSharedMemorySize, GSMEM_BYTES);
    cudaFuncSetAttribute(attn_mma, cudaFuncAttributeMaxDynamicSharedMemorySize, ASMEM);

    const int NX = BB*NN*DD;
    const int NW = DD*DD;

    split_x_kernel<<<NX/512, 256>>>(x, xh, xl, NX/2);
    round_w4_kernel<<<dim3(NW/512, 4), 256>>>((const float*)d_in[2], (const float*)d_in[3],
                                              (const float*)d_in[4], (const float*)d_in[5],
                                              wq, NW/2);

    dim3 gqkv(DD/128, (BB*NN)/128, 3);
    gemm_mma<1><<<gqkv, 256, GSMEM_BYTES>>>(xh, xl, wq, nullptr, qh, ql, kk);

    attn_mma<<<dim3(BH, NN/128), 256, ASMEM>>>(bias);

    gemm_mma<0><<<dim3(DD/128, (BB*NN)/128), 256, GSMEM_BYTES>>>(
        oh, ol, wq + 3*(size_t)NW, out, nullptr, nullptr, nullptr);
}